// round 12
// baseline (speedup 1.0000x reference)
#include <cuda_runtime.h>
#include <cuda_fp16.h>
#include <cstddef>
#include <cstdint>

// Problem constants
#define BATCH   4
#define SEQ     4096
#define DMODEL  1024
#define DSTATE  16
#define DINNER  2048
#define BL      (BATCH*SEQ)          // 16384 rows
#define NCHUNK  32                   // SEQ/128 scan chunks
#define CHUNK   128

// ---------------------------------------------------------------------------
// Scratch (device globals; allocation APIs are forbidden)
// ---------------------------------------------------------------------------
__device__ __half g_xh  [(size_t)BL * DMODEL];      // x in fp16          32MB
__device__ __half g_Winh[(size_t)DMODEL * 2*DINNER];// W_in fp16           8MB
__device__ __half g_Wouth[(size_t)DINNER * DMODEL]; // W_out fp16          4MB
__device__ __half g_xrh [(size_t)BL * (2*DINNER)];  // xr fp16 (main|res) 128MB
__device__ __half g_xch [(size_t)BL * DINNER];      // conv+silu fp16     64MB
__device__ __half g_yh  [(size_t)BL * DINNER];      // gated y fp16       64MB
__device__ float  g_bc[(size_t)BL * 32];            // [Bt | Ct]
__device__ float  g_ys[(size_t)BL];
__device__ float  g_E   [BATCH * NCHUNK * DSTATE];
__device__ float  g_init[BATCH * NCHUNK * DSTATE];

// ===========================================================================
// helpers
// ===========================================================================
#define HBK   32
#define ASTRH 40     // A smem row stride in halves (32 + 8 pad)
#define BSTRH 136    // B smem row stride in halves (128 + 8 pad)
#define A_STAGE (128 * ASTRH)            // halves
#define B_STAGE (HBK * BSTRH)            // halves
#define GEMM_SMEM_BYTES ((3 * (A_STAGE + B_STAGE)) * 2)

__device__ __forceinline__ uint32_t pkh(float a, float b) {
    __half2 h = __floats2half2_rn(a, b);
    return reinterpret_cast<uint32_t&>(h);
}

__device__ __forceinline__ uint32_t smem_u32(const void* p) {
    uint32_t a;
    asm("{ .reg .u64 t; cvta.to.shared.u64 t, %1; cvt.u32.u64 %0, t; }"
        : "=r"(a) : "l"(p));
    return a;
}

__device__ __forceinline__ void cpa16(uint32_t dst_smem, const void* src_gmem) {
    asm volatile("cp.async.cg.shared.global [%0], [%1], 16;"
                 :: "r"(dst_smem), "l"(src_gmem));
}

__device__ __forceinline__ void ldsm_x4(uint32_t r[4], uint32_t addr) {
    asm volatile("ldmatrix.sync.aligned.m8n8.x4.shared.b16 {%0,%1,%2,%3}, [%4];"
        : "=r"(r[0]), "=r"(r[1]), "=r"(r[2]), "=r"(r[3]) : "r"(addr));
}
__device__ __forceinline__ void ldsm_x4t(uint32_t r[4], uint32_t addr) {
    asm volatile("ldmatrix.sync.aligned.m8n8.x4.trans.shared.b16 {%0,%1,%2,%3}, [%4];"
        : "=r"(r[0]), "=r"(r[1]), "=r"(r[2]), "=r"(r[3]) : "r"(addr));
}

__device__ __forceinline__ void mma_f16(float d[4], const uint32_t a[4], const uint32_t b0, const uint32_t b1) {
    asm volatile(
        "mma.sync.aligned.m16n8k16.row.col.f32.f16.f16.f32 "
        "{%0,%1,%2,%3}, {%4,%5,%6,%7}, {%8,%9}, {%0,%1,%2,%3};\n"
        : "+f"(d[0]), "+f"(d[1]), "+f"(d[2]), "+f"(d[3])
        : "r"(a[0]), "r"(a[1]), "r"(a[2]), "r"(a[3]), "r"(b0), "r"(b1));
}

// ===========================================================================
// fp32 -> fp16 elementwise convert (8 elems/thread)
// ===========================================================================
__global__ void cvt_f32_f16(const float* __restrict__ src, __half* __restrict__ dst)
{
    size_t i8 = ((size_t)blockIdx.x * 256 + threadIdx.x) * 8;
    float4 a = *(const float4*)&src[i8];
    float4 b = *(const float4*)&src[i8 + 4];
    uint4 u = make_uint4(pkh(a.x, a.y), pkh(a.z, a.w), pkh(b.x, b.y), pkh(b.z, b.w));
    *(uint4*)&dst[i8] = u;
}

// ===========================================================================
// All-fp16-operand GEMM: C[M,N] = A[M,K]*B[K,N], A,B fp16 row-major,
// fp32 accumulate. 128x128 tile, BK=32, 256 threads, warp tile 64x32,
// 3-stage cp.async pipeline + ldmatrix + m16n8k16.
// __launch_bounds__(256,3): cap regs at 85 -> 3 CTAs/SM (24 warps, 37.5% occ)
// OUTH: write C as fp16 (packed) else fp32.
// ===========================================================================
template <bool OUTH>
__global__ __launch_bounds__(256, 3)
void h16gemm_hh(const __half* __restrict__ A, const __half* __restrict__ B,
                void* __restrict__ Cv, int M, int N, int K)
{
    extern __shared__ char raw[];
    __half* smA = (__half*)raw;                       // 3 stages of A
    __half* smB = (__half*)raw + 3 * A_STAGE;         // 3 stages of B
    const uint32_t smA0 = smem_u32(smA);
    const uint32_t smB0 = smem_u32(smB);

    const int tid  = threadIdx.x;
    const int lane = tid & 31;
    const int wid  = tid >> 5;
    const int wm   = wid >> 2;
    const int wn   = wid & 3;
    const int m0   = blockIdx.y * 128;
    const int n0   = blockIdx.x * 128;
    const int g    = lane >> 2;
    const int t    = lane & 3;
    const int grp  = lane >> 3;
    const int wi   = lane & 7;

    float acc[4][4][4];
#pragma unroll
    for (int mi = 0; mi < 4; mi++)
#pragma unroll
        for (int ni = 0; ni < 4; ni++)
#pragma unroll
            for (int r = 0; r < 4; r++) acc[mi][ni][r] = 0.f;

    const int NT = K / HBK;

    auto issue = [&](int kt) {
        const int s = kt % 3;
        const uint32_t aB = smA0 + s * A_STAGE * 2;
        const __half* Ag = A + (size_t)m0 * K + kt * HBK;
#pragma unroll
        for (int i = 0; i < 2; i++) {
            int idx = tid + i * 256;            // 512 chunks over 128 rows x 4
            int r = idx >> 2, c8 = (idx & 3) * 8;
            cpa16(aB + (uint32_t)(r * ASTRH + c8) * 2, Ag + (size_t)r * K + c8);
        }
        const uint32_t bB = smB0 + s * B_STAGE * 2;
        const __half* Bg = B + (size_t)(kt * HBK) * N + n0;
#pragma unroll
        for (int i = 0; i < 2; i++) {
            int idx = tid + i * 256;            // 512 chunks over 32 rows x 16
            int kr = idx >> 4, c8 = (idx & 15) * 8;
            cpa16(bB + (uint32_t)(kr * BSTRH + c8) * 2, Bg + (size_t)kr * N + c8);
        }
        asm volatile("cp.async.commit_group;");
    };

    issue(0);
    if (NT > 1) issue(1);

    for (int kt = 0; kt < NT; kt++) {
        if (kt + 1 < NT) asm volatile("cp.async.wait_group 1;");
        else             asm volatile("cp.async.wait_group 0;");
        __syncthreads();
        if (kt + 2 < NT) issue(kt + 2);

        const int s = kt % 3;
        const uint32_t asB = smA0 + s * A_STAGE * 2;
        const uint32_t bsB = smB0 + s * B_STAGE * 2;

#pragma unroll
        for (int ks = 0; ks < 2; ks++) {
            const int kh = ks * 16;
            uint32_t af[4][4], bq[2][4];
#pragma unroll
            for (int mi = 0; mi < 4; mi++) {
                int row  = wm * 64 + mi * 16 + (grp & 1) * 8 + wi;
                int colh = kh + (grp >> 1) * 8;
                ldsm_x4(af[mi], asB + (uint32_t)(row * ASTRH + colh) * 2);
            }
#pragma unroll
            for (int p = 0; p < 2; p++) {
                int krow = kh + (grp & 1) * 8 + wi;
                int ncol = wn * 32 + p * 16 + (grp >> 1) * 8;
                ldsm_x4t(bq[p], bsB + (uint32_t)(krow * BSTRH + ncol) * 2);
            }
#pragma unroll
            for (int mi = 0; mi < 4; mi++) {
                mma_f16(acc[mi][0], af[mi], bq[0][0], bq[0][1]);
                mma_f16(acc[mi][1], af[mi], bq[0][2], bq[0][3]);
                mma_f16(acc[mi][2], af[mi], bq[1][0], bq[1][1]);
                mma_f16(acc[mi][3], af[mi], bq[1][2], bq[1][3]);
            }
        }
    }

    // Epilogue: thread owns (g, 2t),(g,2t+1) and (g+8, ...) per 16x8 frag
#pragma unroll
    for (int mi = 0; mi < 4; mi++) {
#pragma unroll
        for (int ni = 0; ni < 4; ni++) {
            int r = m0 + wm * 64 + mi * 16 + g;
            int c = n0 + wn * 32 + ni * 8 + t * 2;
            if (OUTH) {
                __half* Ch = (__half*)Cv;
                *(uint32_t*)&Ch[(size_t)r * N + c]       = pkh(acc[mi][ni][0], acc[mi][ni][1]);
                *(uint32_t*)&Ch[(size_t)(r + 8) * N + c] = pkh(acc[mi][ni][2], acc[mi][ni][3]);
            } else {
                float* Cf = (float*)Cv;
                *(float2*)&Cf[(size_t)r * N + c]       = make_float2(acc[mi][ni][0], acc[mi][ni][1]);
                *(float2*)&Cf[(size_t)(r + 8) * N + c] = make_float2(acc[mi][ni][2], acc[mi][ni][3]);
            }
        }
    }
}

// ---------------------------------------------------------------------------
// Depthwise conv (k=3, pad 1, seq dim) + bias + SiLU; fp16 in/out, fp32 math.
// One thread per 8 consecutive channels of one (b,l) row.
// ---------------------------------------------------------------------------
__global__ void conv_silu(const float* __restrict__ conv_w, const float* __restrict__ conv_b)
{
    size_t vidx = (size_t)blockIdx.x * 256 + threadIdx.x;  // over BL*DINNER/8
    int c8  = (int)((vidx & (DINNER/8 - 1)) << 3);
    size_t row = vidx >> 8;                                // /(DINNER/8)
    int l = (int)(row & (SEQ - 1));

    const __half* base1 = &g_xrh[row * (size_t)(2*DINNER) + c8];
    uint4 u1 = *(const uint4*)base1;
    uint4 u0 = (l > 0)       ? *(const uint4*)(base1 - 2*DINNER) : make_uint4(0,0,0,0);
    uint4 u2 = (l < SEQ - 1) ? *(const uint4*)(base1 + 2*DINNER) : make_uint4(0,0,0,0);

    const __half2* h0 = (const __half2*)&u0;
    const __half2* h1 = (const __half2*)&u1;
    const __half2* h2 = (const __half2*)&u2;

    uint4 out;
    uint32_t* op = (uint32_t*)&out;
#pragma unroll
    for (int p = 0; p < 4; p++) {          // pairs of channels
        float2 f0 = __half22float2(h0[p]);
        float2 f1 = __half22float2(h1[p]);
        float2 f2 = __half22float2(h2[p]);
        int c = c8 + p * 2;
        float a0 = f0.x * conv_w[c*3+0] + f1.x * conv_w[c*3+1] + f2.x * conv_w[c*3+2] + conv_b[c];
        float a1 = f0.y * conv_w[(c+1)*3+0] + f1.y * conv_w[(c+1)*3+1] + f2.y * conv_w[(c+1)*3+2] + conv_b[c+1];
        float s0 = a0 / (1.f + expf(-a0));
        float s1 = a1 / (1.f + expf(-a1));
        op[p] = pkh(s0, s1);
    }
    *(uint4*)&g_xch[row * (size_t)DINNER + c8] = out;
}

// ---------------------------------------------------------------------------
// Skinny GEMM: [Bt|Ct] (BL x 32) = xc(fp16) (BL x 2048) * [W_B | W_C](fp32)
// ---------------------------------------------------------------------------
__global__ __launch_bounds__(256, 4)
void bc_gemm(const float* __restrict__ Wb, const float* __restrict__ Wc)
{
    __shared__ float xs[128][32];
    __shared__ float ws[32][32];

    const int row0 = blockIdx.x * 128;
    const int tid  = threadIdx.x;
    const int tx = tid & 31;
    const int ty = tid >> 5;

    float acc[16];
#pragma unroll
    for (int r = 0; r < 16; r++) acc[r] = 0.f;

    for (int k0 = 0; k0 < DINNER; k0 += 32) {
        __syncthreads();
#pragma unroll
        for (int i = 0; i < 2; i++) {
            int lin = tid + i * 256;           // 512 uint4 over 128 rows x 4
            int r = lin >> 2, c8 = (lin & 3) * 8;
            uint4 u = *(const uint4*)&g_xch[(size_t)(row0 + r) * DINNER + k0 + c8];
            const __half2* hp = (const __half2*)&u;
#pragma unroll
            for (int p = 0; p < 4; p++) {
                float2 f = __half22float2(hp[p]);
                xs[r][c8 + 2*p]     = f.x;
                xs[r][c8 + 2*p + 1] = f.y;
            }
        }
        {
            int lin = tid * 4;
            int kk = lin >> 5, c = lin & 31;
            float4 v;
            if (c < 16) v = *(const float4*)&Wb[(size_t)(k0 + kk) * 16 + c];
            else        v = *(const float4*)&Wc[(size_t)(k0 + kk) * 16 + (c - 16)];
            *(float4*)&ws[kk][c] = v;
        }
        __syncthreads();

#pragma unroll
        for (int kk = 0; kk < 32; kk++) {
            float w = ws[kk][tx];
#pragma unroll
            for (int r = 0; r < 16; r++)
                acc[r] += xs[ty * 16 + r][kk] * w;
        }
    }

#pragma unroll
    for (int r = 0; r < 16; r++)
        g_bc[(size_t)(row0 + ty * 16 + r) * 32 + tx] = acc[r];
}

// ---------------------------------------------------------------------------
// Chunked scan: phase A (chunk end-states from 0), combine, phase C (replay).
// ---------------------------------------------------------------------------
__global__ void scan_phaseA(const float* __restrict__ A)
{
    __shared__ float bcs[CHUNK][32];
    const int b = blockIdx.x >> 5;
    const int c = blockIdx.x & 31;
    const int tid = threadIdx.x;

    const size_t base = (size_t)b * SEQ + (size_t)c * CHUNK;
    const size_t grow = (base + tid) * 32;
#pragma unroll
    for (int i = 0; i < 8; i++)
        *(float4*)&bcs[tid][i * 4] = *(const float4*)&g_bc[grow + i * 4];
    __syncthreads();

    if (tid < DSTATE) {
        float dec = 1.f / (1.f + expf(A[tid]));
        float st = 0.f;
        for (int l = 0; l < CHUNK; l++)
            st = fmaf(st, dec, bcs[l][tid]);
        g_E[(b * NCHUNK + c) * DSTATE + tid] = st;
    }
}

__global__ void scan_combine(const float* __restrict__ A)
{
    const int b = blockIdx.x;
    const int s = threadIdx.x;
    float dec  = 1.f / (1.f + expf(A[s]));
    float d128 = powf(dec, (float)CHUNK);
    float S = 0.f;
    for (int c = 0; c < NCHUNK; c++) {
        g_init[(b * NCHUNK + c) * DSTATE + s] = S;
        S = S * d128 + g_E[(b * NCHUNK + c) * DSTATE + s];
    }
}

__global__ void scan_phaseC(const float* __restrict__ A)
{
    __shared__ float bcs[CHUNK][32];
    const int b = blockIdx.x >> 5;
    const int c = blockIdx.x & 31;
    const int tid = threadIdx.x;

    const size_t base = (size_t)b * SEQ + (size_t)c * CHUNK;
    const size_t grow = (base + tid) * 32;
#pragma unroll
    for (int i = 0; i < 8; i++)
        *(float4*)&bcs[tid][i * 4] = *(const float4*)&g_bc[grow + i * 4];
    __syncthreads();

    if (tid < DSTATE) {
        float dec = 1.f / (1.f + expf(A[tid]));
        float st = g_init[(b * NCHUNK + c) * DSTATE + tid];
        for (int l = 0; l < CHUNK; l++) {
            st = fmaf(st, dec, bcs[l][tid]);
            float v = st * bcs[l][16 + tid];
#pragma unroll
            for (int m = 8; m >= 1; m >>= 1)
                v += __shfl_xor_sync(0x0000ffffu, v, m, 16);
            if (tid == 0) g_ys[base + l] = v;
        }
    }
}

// ---------------------------------------------------------------------------
// Gating elementwise (fp16 in/out): yh = half((ys + xc*D) * silu(res))
// ---------------------------------------------------------------------------
__global__ void gate_y(const float* __restrict__ Dv)
{
    size_t vidx = (size_t)blockIdx.x * 256 + threadIdx.x;  // over BL*DINNER/8
    int c8  = (int)((vidx & (DINNER/8 - 1)) << 3);
    size_t row = vidx >> 8;

    uint4 uxc  = *(const uint4*)&g_xch[row * (size_t)DINNER + c8];
    uint4 ures = *(const uint4*)&g_xrh[row * (size_t)(2*DINNER) + DINNER + c8];
    const __half2* hxc  = (const __half2*)&uxc;
    const __half2* hres = (const __half2*)&ures;
    float ysv = g_ys[row];

    uint4 out;
    uint32_t* op = (uint32_t*)&out;
#pragma unroll
    for (int p = 0; p < 4; p++) {
        float2 xc  = __half22float2(hxc[p]);
        float2 res = __half22float2(hres[p]);
        int c = c8 + p * 2;
        float y0 = (ysv + xc.x * Dv[c])     * (res.x / (1.f + expf(-res.x)));
        float y1 = (ysv + xc.y * Dv[c + 1]) * (res.y / (1.f + expf(-res.y)));
        op[p] = pkh(y0, y1);
    }
    *(uint4*)&g_yh[row * (size_t)DINNER + c8] = out;
}

// ---------------------------------------------------------------------------
// Launch
// ---------------------------------------------------------------------------
extern "C" void kernel_launch(void* const* d_in, const int* in_sizes, int n_in,
                              void* d_out, int out_size)
{
    const float* x      = (const float*)d_in[0];
    const float* W_in   = (const float*)d_in[1];
    const float* conv_w = (const float*)d_in[2];
    const float* conv_b = (const float*)d_in[3];
    const float* W_B    = (const float*)d_in[4];
    const float* W_C    = (const float*)d_in[5];
    const float* A      = (const float*)d_in[6];
    const float* Dv     = (const float*)d_in[7];
    const float* W_out  = (const float*)d_in[8];
    float* out = (float*)d_out;

    __half *xh_p, *winh_p, *wouth_p, *xrh_p, *yh_p;
    cudaGetSymbolAddress((void**)&xh_p,   g_xh);
    cudaGetSymbolAddress((void**)&winh_p, g_Winh);
    cudaGetSymbolAddress((void**)&wouth_p,g_Wouth);
    cudaGetSymbolAddress((void**)&xrh_p,  g_xrh);
    cudaGetSymbolAddress((void**)&yh_p,   g_yh);

    cudaFuncSetAttribute(h16gemm_hh<true>,  cudaFuncAttributeMaxDynamicSharedMemorySize, GEMM_SMEM_BYTES);
    cudaFuncSetAttribute(h16gemm_hh<false>, cudaFuncAttributeMaxDynamicSharedMemorySize, GEMM_SMEM_BYTES);

    // 0) fp32 -> fp16 conversions (x, W_in, W_out)
    cvt_f32_f16<<<((size_t)BL * DMODEL / 8) / 256, 256>>>(x, xh_p);
    cvt_f32_f16<<<((size_t)DMODEL * 2*DINNER / 8) / 256, 256>>>(W_in, winh_p);
    cvt_f32_f16<<<((size_t)DINNER * DMODEL / 8) / 256, 256>>>(W_out, wouth_p);

    // 1) xr(fp16) = x @ W_in   [all-fp16 operands, fp16 out]
    {
        dim3 grid((2*DINNER) / 128, BL / 128);
        h16gemm_hh<true><<<grid, 256, GEMM_SMEM_BYTES>>>(xh_p, winh_p, xrh_p, BL, 2*DINNER, DMODEL);
    }
    // 2) depthwise conv + bias + silu -> xc (fp16)
    conv_silu<<<((size_t)BL * DINNER / 8) / 256, 256>>>(conv_w, conv_b);
    // 3) [Bt|Ct] = xc @ [W_B|W_C]
    bc_gemm<<<BL / 128, 256>>>(W_B, W_C);
    // 4) chunked scan -> ys
    scan_phaseA<<<BATCH * NCHUNK, CHUNK>>>(A);
    scan_combine<<<BATCH, DSTATE>>>(A);
    scan_phaseC<<<BATCH * NCHUNK, CHUNK>>>(A);
    // 5) gating -> yh (fp16)
    gate_y<<<((size_t)BL * DINNER / 8) / 256, 256>>>(Dv);
    // 6) out(fp32) = yh @ W_out  [all-fp16 operands]
    {
        dim3 grid(DMODEL / 128, BL / 128);
        h16gemm_hh<false><<<grid, 256, GEMM_SMEM_BYTES>>>(yh_p, wouth_p, out, BL, DMODEL, DINNER);
    }
}

// round 13
// speedup vs baseline: 1.2506x; 1.2506x over previous
#include <cuda_runtime.h>
#include <cuda_fp16.h>
#include <cstddef>
#include <cstdint>

// Problem constants
#define BATCH   4
#define SEQ     4096
#define DMODEL  1024
#define DSTATE  16
#define DINNER  2048
#define BL      (BATCH*SEQ)          // 16384 rows
#define NCHUNK  32                   // SEQ/128 scan chunks
#define CHUNK   128

// ---------------------------------------------------------------------------
// Scratch (device globals; allocation APIs are forbidden)
// ---------------------------------------------------------------------------
__device__ __half g_xh  [(size_t)BL * DMODEL];      // x in fp16          32MB
__device__ __half g_Winh[(size_t)DMODEL * 2*DINNER];// W_in fp16           8MB
__device__ __half g_Wouth[(size_t)DINNER * DMODEL]; // W_out fp16          4MB
__device__ __half g_xrh [(size_t)BL * (2*DINNER)];  // xr fp16 (main|res) 128MB
__device__ __half g_xch [(size_t)BL * DINNER];      // conv+silu fp16     64MB
__device__ __half g_yh  [(size_t)BL * DINNER];      // gated y fp16       64MB
__device__ float  g_bc[(size_t)BL * 32];            // [Bt | Ct]
__device__ float  g_ys[(size_t)BL];
__device__ float  g_E   [BATCH * NCHUNK * DSTATE];
__device__ float  g_init[BATCH * NCHUNK * DSTATE];

// ===========================================================================
// helpers
// ===========================================================================
#define HBK   64
#define ASTRH 72     // A smem row stride in halves (64 + 8 pad)
#define BSTRH 136    // B smem row stride in halves (128 + 8 pad)
#define A_STAGE (128 * ASTRH)            // halves
#define B_STAGE (HBK * BSTRH)            // halves
#define GEMM_SMEM_BYTES ((3 * (A_STAGE + B_STAGE)) * 2)

__device__ __forceinline__ uint32_t pkh(float a, float b) {
    __half2 h = __floats2half2_rn(a, b);
    return reinterpret_cast<uint32_t&>(h);
}

__device__ __forceinline__ uint32_t smem_u32(const void* p) {
    uint32_t a;
    asm("{ .reg .u64 t; cvta.to.shared.u64 t, %1; cvt.u32.u64 %0, t; }"
        : "=r"(a) : "l"(p));
    return a;
}

__device__ __forceinline__ void cpa16(uint32_t dst_smem, const void* src_gmem) {
    asm volatile("cp.async.cg.shared.global [%0], [%1], 16;"
                 :: "r"(dst_smem), "l"(src_gmem));
}

__device__ __forceinline__ void ldsm_x4(uint32_t r[4], uint32_t addr) {
    asm volatile("ldmatrix.sync.aligned.m8n8.x4.shared.b16 {%0,%1,%2,%3}, [%4];"
        : "=r"(r[0]), "=r"(r[1]), "=r"(r[2]), "=r"(r[3]) : "r"(addr));
}
__device__ __forceinline__ void ldsm_x4t(uint32_t r[4], uint32_t addr) {
    asm volatile("ldmatrix.sync.aligned.m8n8.x4.trans.shared.b16 {%0,%1,%2,%3}, [%4];"
        : "=r"(r[0]), "=r"(r[1]), "=r"(r[2]), "=r"(r[3]) : "r"(addr));
}

__device__ __forceinline__ void mma_f16(float d[4], const uint32_t a[4], const uint32_t b0, const uint32_t b1) {
    asm volatile(
        "mma.sync.aligned.m16n8k16.row.col.f32.f16.f16.f32 "
        "{%0,%1,%2,%3}, {%4,%5,%6,%7}, {%8,%9}, {%0,%1,%2,%3};\n"
        : "+f"(d[0]), "+f"(d[1]), "+f"(d[2]), "+f"(d[3])
        : "r"(a[0]), "r"(a[1]), "r"(a[2]), "r"(a[3]), "r"(b0), "r"(b1));
}

// ===========================================================================
// fp32 -> fp16 elementwise convert (8 elems/thread)
// ===========================================================================
__global__ void cvt_f32_f16(const float* __restrict__ src, __half* __restrict__ dst)
{
    size_t i8 = ((size_t)blockIdx.x * 256 + threadIdx.x) * 8;
    float4 a = *(const float4*)&src[i8];
    float4 b = *(const float4*)&src[i8 + 4];
    uint4 u = make_uint4(pkh(a.x, a.y), pkh(a.z, a.w), pkh(b.x, b.y), pkh(b.z, b.w));
    *(uint4*)&dst[i8] = u;
}

// ===========================================================================
// All-fp16-operand GEMM: C[M,N] = A[M,K]*B[K,N], A,B fp16 row-major,
// fp32 accumulate. 128x128 tile, BK=64, 256 threads, warp tile 64x32,
// 3-stage cp.async pipeline + ldmatrix + m16n8k16.
// (No occupancy cap: R12 showed the 85-reg squeeze spills; 94 regs / 2 CTAs
//  is the right point. BK=64 halves sync+commit overhead instead.)
// OUTH: write C as fp16 (packed) else fp32.
// ===========================================================================
template <bool OUTH>
__global__ __launch_bounds__(256)
void h16gemm_hh(const __half* __restrict__ A, const __half* __restrict__ B,
                void* __restrict__ Cv, int M, int N, int K)
{
    extern __shared__ char raw[];
    __half* smA = (__half*)raw;                       // 3 stages of A
    __half* smB = (__half*)raw + 3 * A_STAGE;         // 3 stages of B
    const uint32_t smA0 = smem_u32(smA);
    const uint32_t smB0 = smem_u32(smB);

    const int tid  = threadIdx.x;
    const int lane = tid & 31;
    const int wid  = tid >> 5;
    const int wm   = wid >> 2;
    const int wn   = wid & 3;
    const int m0   = blockIdx.y * 128;
    const int n0   = blockIdx.x * 128;
    const int g    = lane >> 2;
    const int t    = lane & 3;
    const int grp  = lane >> 3;
    const int wi   = lane & 7;

    float acc[4][4][4];
#pragma unroll
    for (int mi = 0; mi < 4; mi++)
#pragma unroll
        for (int ni = 0; ni < 4; ni++)
#pragma unroll
            for (int r = 0; r < 4; r++) acc[mi][ni][r] = 0.f;

    const int NT = K / HBK;

    auto issue = [&](int kt) {
        const int s = kt % 3;
        const uint32_t aB = smA0 + s * A_STAGE * 2;
        const __half* Ag = A + (size_t)m0 * K + kt * HBK;
#pragma unroll
        for (int i = 0; i < 4; i++) {
            int idx = tid + i * 256;            // 1024 chunks over 128 rows x 8
            int r = idx >> 3, c8 = (idx & 7) * 8;
            cpa16(aB + (uint32_t)(r * ASTRH + c8) * 2, Ag + (size_t)r * K + c8);
        }
        const uint32_t bB = smB0 + s * B_STAGE * 2;
        const __half* Bg = B + (size_t)(kt * HBK) * N + n0;
#pragma unroll
        for (int i = 0; i < 4; i++) {
            int idx = tid + i * 256;            // 1024 chunks over 64 rows x 16
            int kr = idx >> 4, c8 = (idx & 15) * 8;
            cpa16(bB + (uint32_t)(kr * BSTRH + c8) * 2, Bg + (size_t)kr * N + c8);
        }
        asm volatile("cp.async.commit_group;");
    };

    issue(0);
    if (NT > 1) issue(1);

    for (int kt = 0; kt < NT; kt++) {
        if (kt + 1 < NT) asm volatile("cp.async.wait_group 1;");
        else             asm volatile("cp.async.wait_group 0;");
        __syncthreads();
        if (kt + 2 < NT) issue(kt + 2);

        const int s = kt % 3;
        const uint32_t asB = smA0 + s * A_STAGE * 2;
        const uint32_t bsB = smB0 + s * B_STAGE * 2;

#pragma unroll
        for (int ks = 0; ks < 4; ks++) {        // four k16 steps per BK=64
            const int kh = ks * 16;
            uint32_t af[4][4], bq[2][4];
#pragma unroll
            for (int mi = 0; mi < 4; mi++) {
                int row  = wm * 64 + mi * 16 + (grp & 1) * 8 + wi;
                int colh = kh + (grp >> 1) * 8;
                ldsm_x4(af[mi], asB + (uint32_t)(row * ASTRH + colh) * 2);
            }
#pragma unroll
            for (int p = 0; p < 2; p++) {
                int krow = kh + (grp & 1) * 8 + wi;
                int ncol = wn * 32 + p * 16 + (grp >> 1) * 8;
                ldsm_x4t(bq[p], bsB + (uint32_t)(krow * BSTRH + ncol) * 2);
            }
#pragma unroll
            for (int mi = 0; mi < 4; mi++) {
                mma_f16(acc[mi][0], af[mi], bq[0][0], bq[0][1]);
                mma_f16(acc[mi][1], af[mi], bq[0][2], bq[0][3]);
                mma_f16(acc[mi][2], af[mi], bq[1][0], bq[1][1]);
                mma_f16(acc[mi][3], af[mi], bq[1][2], bq[1][3]);
            }
        }
    }

    // Epilogue: thread owns (g, 2t),(g,2t+1) and (g+8, ...) per 16x8 frag
#pragma unroll
    for (int mi = 0; mi < 4; mi++) {
#pragma unroll
        for (int ni = 0; ni < 4; ni++) {
            int r = m0 + wm * 64 + mi * 16 + g;
            int c = n0 + wn * 32 + ni * 8 + t * 2;
            if (OUTH) {
                __half* Ch = (__half*)Cv;
                *(uint32_t*)&Ch[(size_t)r * N + c]       = pkh(acc[mi][ni][0], acc[mi][ni][1]);
                *(uint32_t*)&Ch[(size_t)(r + 8) * N + c] = pkh(acc[mi][ni][2], acc[mi][ni][3]);
            } else {
                float* Cf = (float*)Cv;
                *(float2*)&Cf[(size_t)r * N + c]       = make_float2(acc[mi][ni][0], acc[mi][ni][1]);
                *(float2*)&Cf[(size_t)(r + 8) * N + c] = make_float2(acc[mi][ni][2], acc[mi][ni][3]);
            }
        }
    }
}

// ---------------------------------------------------------------------------
// Depthwise conv (k=3, pad 1, seq dim) + bias + SiLU; fp16 in/out, fp32 math.
// One thread per 8 consecutive channels of one (b,l) row.
// ---------------------------------------------------------------------------
__global__ void conv_silu(const float* __restrict__ conv_w, const float* __restrict__ conv_b)
{
    size_t vidx = (size_t)blockIdx.x * 256 + threadIdx.x;  // over BL*DINNER/8
    int c8  = (int)((vidx & (DINNER/8 - 1)) << 3);
    size_t row = vidx >> 8;                                // /(DINNER/8)
    int l = (int)(row & (SEQ - 1));

    const __half* base1 = &g_xrh[row * (size_t)(2*DINNER) + c8];
    uint4 u1 = *(const uint4*)base1;
    uint4 u0 = (l > 0)       ? *(const uint4*)(base1 - 2*DINNER) : make_uint4(0,0,0,0);
    uint4 u2 = (l < SEQ - 1) ? *(const uint4*)(base1 + 2*DINNER) : make_uint4(0,0,0,0);

    const __half2* h0 = (const __half2*)&u0;
    const __half2* h1 = (const __half2*)&u1;
    const __half2* h2 = (const __half2*)&u2;

    uint4 out;
    uint32_t* op = (uint32_t*)&out;
#pragma unroll
    for (int p = 0; p < 4; p++) {          // pairs of channels
        float2 f0 = __half22float2(h0[p]);
        float2 f1 = __half22float2(h1[p]);
        float2 f2 = __half22float2(h2[p]);
        int c = c8 + p * 2;
        float a0 = f0.x * conv_w[c*3+0] + f1.x * conv_w[c*3+1] + f2.x * conv_w[c*3+2] + conv_b[c];
        float a1 = f0.y * conv_w[(c+1)*3+0] + f1.y * conv_w[(c+1)*3+1] + f2.y * conv_w[(c+1)*3+2] + conv_b[c+1];
        float s0 = a0 / (1.f + expf(-a0));
        float s1 = a1 / (1.f + expf(-a1));
        op[p] = pkh(s0, s1);
    }
    *(uint4*)&g_xch[row * (size_t)DINNER + c8] = out;
}

// ---------------------------------------------------------------------------
// Skinny GEMM: [Bt|Ct] (BL x 32) = xc(fp16) (BL x 2048) * [W_B | W_C](fp32)
// ---------------------------------------------------------------------------
__global__ __launch_bounds__(256, 4)
void bc_gemm(const float* __restrict__ Wb, const float* __restrict__ Wc)
{
    __shared__ float xs[128][32];
    __shared__ float ws[32][32];

    const int row0 = blockIdx.x * 128;
    const int tid  = threadIdx.x;
    const int tx = tid & 31;
    const int ty = tid >> 5;

    float acc[16];
#pragma unroll
    for (int r = 0; r < 16; r++) acc[r] = 0.f;

    for (int k0 = 0; k0 < DINNER; k0 += 32) {
        __syncthreads();
#pragma unroll
        for (int i = 0; i < 2; i++) {
            int lin = tid + i * 256;           // 512 uint4 over 128 rows x 4
            int r = lin >> 2, c8 = (lin & 3) * 8;
            uint4 u = *(const uint4*)&g_xch[(size_t)(row0 + r) * DINNER + k0 + c8];
            const __half2* hp = (const __half2*)&u;
#pragma unroll
            for (int p = 0; p < 4; p++) {
                float2 f = __half22float2(hp[p]);
                xs[r][c8 + 2*p]     = f.x;
                xs[r][c8 + 2*p + 1] = f.y;
            }
        }
        {
            int lin = tid * 4;
            int kk = lin >> 5, c = lin & 31;
            float4 v;
            if (c < 16) v = *(const float4*)&Wb[(size_t)(k0 + kk) * 16 + c];
            else        v = *(const float4*)&Wc[(size_t)(k0 + kk) * 16 + (c - 16)];
            *(float4*)&ws[kk][c] = v;
        }
        __syncthreads();

#pragma unroll
        for (int kk = 0; kk < 32; kk++) {
            float w = ws[kk][tx];
#pragma unroll
            for (int r = 0; r < 16; r++)
                acc[r] += xs[ty * 16 + r][kk] * w;
        }
    }

#pragma unroll
    for (int r = 0; r < 16; r++)
        g_bc[(size_t)(row0 + ty * 16 + r) * 32 + tx] = acc[r];
}

// ---------------------------------------------------------------------------
// Chunked scan: phase A (chunk end-states from 0), combine, phase C (replay).
// ---------------------------------------------------------------------------
__global__ void scan_phaseA(const float* __restrict__ A)
{
    __shared__ float bcs[CHUNK][32];
    const int b = blockIdx.x >> 5;
    const int c = blockIdx.x & 31;
    const int tid = threadIdx.x;

    const size_t base = (size_t)b * SEQ + (size_t)c * CHUNK;
    const size_t grow = (base + tid) * 32;
#pragma unroll
    for (int i = 0; i < 8; i++)
        *(float4*)&bcs[tid][i * 4] = *(const float4*)&g_bc[grow + i * 4];
    __syncthreads();

    if (tid < DSTATE) {
        float dec = 1.f / (1.f + expf(A[tid]));
        float st = 0.f;
        for (int l = 0; l < CHUNK; l++)
            st = fmaf(st, dec, bcs[l][tid]);
        g_E[(b * NCHUNK + c) * DSTATE + tid] = st;
    }
}

__global__ void scan_combine(const float* __restrict__ A)
{
    const int b = blockIdx.x;
    const int s = threadIdx.x;
    float dec  = 1.f / (1.f + expf(A[s]));
    float d128 = powf(dec, (float)CHUNK);
    float S = 0.f;
    for (int c = 0; c < NCHUNK; c++) {
        g_init[(b * NCHUNK + c) * DSTATE + s] = S;
        S = S * d128 + g_E[(b * NCHUNK + c) * DSTATE + s];
    }
}

__global__ void scan_phaseC(const float* __restrict__ A)
{
    __shared__ float bcs[CHUNK][32];
    const int b = blockIdx.x >> 5;
    const int c = blockIdx.x & 31;
    const int tid = threadIdx.x;

    const size_t base = (size_t)b * SEQ + (size_t)c * CHUNK;
    const size_t grow = (base + tid) * 32;
#pragma unroll
    for (int i = 0; i < 8; i++)
        *(float4*)&bcs[tid][i * 4] = *(const float4*)&g_bc[grow + i * 4];
    __syncthreads();

    if (tid < DSTATE) {
        float dec = 1.f / (1.f + expf(A[tid]));
        float st = g_init[(b * NCHUNK + c) * DSTATE + tid];
        for (int l = 0; l < CHUNK; l++) {
            st = fmaf(st, dec, bcs[l][tid]);
            float v = st * bcs[l][16 + tid];
#pragma unroll
            for (int m = 8; m >= 1; m >>= 1)
                v += __shfl_xor_sync(0x0000ffffu, v, m, 16);
            if (tid == 0) g_ys[base + l] = v;
        }
    }
}

// ---------------------------------------------------------------------------
// Gating elementwise (fp16 in/out): yh = half((ys + xc*D) * silu(res))
// ---------------------------------------------------------------------------
__global__ void gate_y(const float* __restrict__ Dv)
{
    size_t vidx = (size_t)blockIdx.x * 256 + threadIdx.x;  // over BL*DINNER/8
    int c8  = (int)((vidx & (DINNER/8 - 1)) << 3);
    size_t row = vidx >> 8;

    uint4 uxc  = *(const uint4*)&g_xch[row * (size_t)DINNER + c8];
    uint4 ures = *(const uint4*)&g_xrh[row * (size_t)(2*DINNER) + DINNER + c8];
    const __half2* hxc  = (const __half2*)&uxc;
    const __half2* hres = (const __half2*)&ures;
    float ysv = g_ys[row];

    uint4 out;
    uint32_t* op = (uint32_t*)&out;
#pragma unroll
    for (int p = 0; p < 4; p++) {
        float2 xc  = __half22float2(hxc[p]);
        float2 res = __half22float2(hres[p]);
        int c = c8 + p * 2;
        float y0 = (ysv + xc.x * Dv[c])     * (res.x / (1.f + expf(-res.x)));
        float y1 = (ysv + xc.y * Dv[c + 1]) * (res.y / (1.f + expf(-res.y)));
        op[p] = pkh(y0, y1);
    }
    *(uint4*)&g_yh[row * (size_t)DINNER + c8] = out;
}

// ---------------------------------------------------------------------------
// Launch
// ---------------------------------------------------------------------------
extern "C" void kernel_launch(void* const* d_in, const int* in_sizes, int n_in,
                              void* d_out, int out_size)
{
    const float* x      = (const float*)d_in[0];
    const float* W_in   = (const float*)d_in[1];
    const float* conv_w = (const float*)d_in[2];
    const float* conv_b = (const float*)d_in[3];
    const float* W_B    = (const float*)d_in[4];
    const float* W_C    = (const float*)d_in[5];
    const float* A      = (const float*)d_in[6];
    const float* Dv     = (const float*)d_in[7];
    const float* W_out  = (const float*)d_in[8];
    float* out = (float*)d_out;

    __half *xh_p, *winh_p, *wouth_p, *xrh_p, *yh_p;
    cudaGetSymbolAddress((void**)&xh_p,   g_xh);
    cudaGetSymbolAddress((void**)&winh_p, g_Winh);
    cudaGetSymbolAddress((void**)&wouth_p,g_Wouth);
    cudaGetSymbolAddress((void**)&xrh_p,  g_xrh);
    cudaGetSymbolAddress((void**)&yh_p,   g_yh);

    cudaFuncSetAttribute(h16gemm_hh<true>,  cudaFuncAttributeMaxDynamicSharedMemorySize, GEMM_SMEM_BYTES);
    cudaFuncSetAttribute(h16gemm_hh<false>, cudaFuncAttributeMaxDynamicSharedMemorySize, GEMM_SMEM_BYTES);

    // 0) fp32 -> fp16 conversions (x, W_in, W_out)
    cvt_f32_f16<<<((size_t)BL * DMODEL / 8) / 256, 256>>>(x, xh_p);
    cvt_f32_f16<<<((size_t)DMODEL * 2*DINNER / 8) / 256, 256>>>(W_in, winh_p);
    cvt_f32_f16<<<((size_t)DINNER * DMODEL / 8) / 256, 256>>>(W_out, wouth_p);

    // 1) xr(fp16) = x @ W_in   [all-fp16 operands, fp16 out]
    {
        dim3 grid((2*DINNER) / 128, BL / 128);
        h16gemm_hh<true><<<grid, 256, GEMM_SMEM_BYTES>>>(xh_p, winh_p, xrh_p, BL, 2*DINNER, DMODEL);
    }
    // 2) depthwise conv + bias + silu -> xc (fp16)
    conv_silu<<<((size_t)BL * DINNER / 8) / 256, 256>>>(conv_w, conv_b);
    // 3) [Bt|Ct] = xc @ [W_B|W_C]
    bc_gemm<<<BL / 128, 256>>>(W_B, W_C);
    // 4) chunked scan -> ys
    scan_phaseA<<<BATCH * NCHUNK, CHUNK>>>(A);
    scan_combine<<<BATCH, DSTATE>>>(A);
    scan_phaseC<<<BATCH * NCHUNK, CHUNK>>>(A);
    // 5) gating -> yh (fp16)
    gate_y<<<((size_t)BL * DINNER / 8) / 256, 256>>>(Dv);
    // 6) out(fp32) = yh @ W_out  [all-fp16 operands]
    {
        dim3 grid(DMODEL / 128, BL / 128);
        h16gemm_hh<false><<<grid, 256, GEMM_SMEM_BYTES>>>(yh_p, wouth_p, out, BL, DMODEL, DINNER);
    }
}

// round 14
// speedup vs baseline: 1.3245x; 1.0591x over previous
#include <cuda_runtime.h>
#include <cuda_fp16.h>
#include <cstddef>
#include <cstdint>

// Problem constants
#define BATCH   4
#define SEQ     4096
#define DMODEL  1024
#define DSTATE  16
#define DINNER  2048
#define BL      (BATCH*SEQ)          // 16384 rows
#define NCHUNK  32                   // SEQ/128 scan chunks
#define CHUNK   128

// ---------------------------------------------------------------------------
// Scratch (device globals; allocation APIs are forbidden)
// ---------------------------------------------------------------------------
__device__ __half g_xh  [(size_t)BL * DMODEL];      // x in fp16          32MB
__device__ __half g_Winh[(size_t)DMODEL * 2*DINNER];// W_in fp16           8MB
__device__ __half g_Wouth[(size_t)DINNER * DMODEL]; // W_out fp16          4MB
__device__ __half g_xrh [(size_t)BL * (2*DINNER)];  // xr fp16 (main|res) 128MB
__device__ __half g_xch [(size_t)BL * DINNER];      // conv+silu fp16     64MB
__device__ __half g_yh  [(size_t)BL * DINNER];      // gated y fp16       64MB
__device__ float  g_bc[(size_t)BL * 32];            // [Bt | Ct]
__device__ float  g_ys[(size_t)BL];
__device__ float  g_E   [BATCH * NCHUNK * DSTATE];
__device__ float  g_init[BATCH * NCHUNK * DSTATE];

// ===========================================================================
// helpers
// ===========================================================================
#define HBK   64
#define ASTRH 72     // A smem row stride in halves (64 + 8 pad)
#define BSTRH 136    // B smem row stride in halves (128 + 8 pad)
#define A_STAGE (128 * ASTRH)            // halves
#define B_STAGE (HBK * BSTRH)            // halves
#define GEMM_SMEM_BYTES ((3 * (A_STAGE + B_STAGE)) * 2)

__device__ __forceinline__ uint32_t pkh(float a, float b) {
    __half2 h = __floats2half2_rn(a, b);
    return reinterpret_cast<uint32_t&>(h);
}

__device__ __forceinline__ uint32_t smem_u32(const void* p) {
    uint32_t a;
    asm("{ .reg .u64 t; cvta.to.shared.u64 t, %1; cvt.u32.u64 %0, t; }"
        : "=r"(a) : "l"(p));
    return a;
}

__device__ __forceinline__ void cpa16(uint32_t dst_smem, const void* src_gmem) {
    asm volatile("cp.async.cg.shared.global [%0], [%1], 16;"
                 :: "r"(dst_smem), "l"(src_gmem));
}

__device__ __forceinline__ void ldsm_x4(uint32_t r[4], uint32_t addr) {
    asm volatile("ldmatrix.sync.aligned.m8n8.x4.shared.b16 {%0,%1,%2,%3}, [%4];"
        : "=r"(r[0]), "=r"(r[1]), "=r"(r[2]), "=r"(r[3]) : "r"(addr));
}
__device__ __forceinline__ void ldsm_x4t(uint32_t r[4], uint32_t addr) {
    asm volatile("ldmatrix.sync.aligned.m8n8.x4.trans.shared.b16 {%0,%1,%2,%3}, [%4];"
        : "=r"(r[0]), "=r"(r[1]), "=r"(r[2]), "=r"(r[3]) : "r"(addr));
}

__device__ __forceinline__ void mma_f16(float d[4], const uint32_t a[4], const uint32_t b0, const uint32_t b1) {
    asm volatile(
        "mma.sync.aligned.m16n8k16.row.col.f32.f16.f16.f32 "
        "{%0,%1,%2,%3}, {%4,%5,%6,%7}, {%8,%9}, {%0,%1,%2,%3};\n"
        : "+f"(d[0]), "+f"(d[1]), "+f"(d[2]), "+f"(d[3])
        : "r"(a[0]), "r"(a[1]), "r"(a[2]), "r"(a[3]), "r"(b0), "r"(b1));
}

// ===========================================================================
// fp32 -> fp16 elementwise convert (8 elems/thread)
// ===========================================================================
__global__ void cvt_f32_f16(const float* __restrict__ src, __half* __restrict__ dst)
{
    size_t i8 = ((size_t)blockIdx.x * 256 + threadIdx.x) * 8;
    float4 a = *(const float4*)&src[i8];
    float4 b = *(const float4*)&src[i8 + 4];
    uint4 u = make_uint4(pkh(a.x, a.y), pkh(a.z, a.w), pkh(b.x, b.y), pkh(b.z, b.w));
    *(uint4*)&dst[i8] = u;
}

// ===========================================================================
// All-fp16-operand GEMM: C[M,N] = A[M,K]*B[K,N], fp32 accumulate.
// 128x128 tile, BK=64, 256 threads, warp tile 64x32, 3-stage cp.async,
// ldmatrix + m16n8k16. (Frozen: R13-verified config.)
// ===========================================================================
template <bool OUTH>
__global__ __launch_bounds__(256)
void h16gemm_hh(const __half* __restrict__ A, const __half* __restrict__ B,
                void* __restrict__ Cv, int M, int N, int K)
{
    extern __shared__ char raw[];
    __half* smA = (__half*)raw;                       // 3 stages of A
    __half* smB = (__half*)raw + 3 * A_STAGE;         // 3 stages of B
    const uint32_t smA0 = smem_u32(smA);
    const uint32_t smB0 = smem_u32(smB);

    const int tid  = threadIdx.x;
    const int lane = tid & 31;
    const int wid  = tid >> 5;
    const int wm   = wid >> 2;
    const int wn   = wid & 3;
    const int m0   = blockIdx.y * 128;
    const int n0   = blockIdx.x * 128;
    const int g    = lane >> 2;
    const int t    = lane & 3;
    const int grp  = lane >> 3;
    const int wi   = lane & 7;

    float acc[4][4][4];
#pragma unroll
    for (int mi = 0; mi < 4; mi++)
#pragma unroll
        for (int ni = 0; ni < 4; ni++)
#pragma unroll
            for (int r = 0; r < 4; r++) acc[mi][ni][r] = 0.f;

    const int NT = K / HBK;

    auto issue = [&](int kt) {
        const int s = kt % 3;
        const uint32_t aB = smA0 + s * A_STAGE * 2;
        const __half* Ag = A + (size_t)m0 * K + kt * HBK;
#pragma unroll
        for (int i = 0; i < 4; i++) {
            int idx = tid + i * 256;            // 1024 chunks over 128 rows x 8
            int r = idx >> 3, c8 = (idx & 7) * 8;
            cpa16(aB + (uint32_t)(r * ASTRH + c8) * 2, Ag + (size_t)r * K + c8);
        }
        const uint32_t bB = smB0 + s * B_STAGE * 2;
        const __half* Bg = B + (size_t)(kt * HBK) * N + n0;
#pragma unroll
        for (int i = 0; i < 4; i++) {
            int idx = tid + i * 256;            // 1024 chunks over 64 rows x 16
            int kr = idx >> 4, c8 = (idx & 15) * 8;
            cpa16(bB + (uint32_t)(kr * BSTRH + c8) * 2, Bg + (size_t)kr * N + c8);
        }
        asm volatile("cp.async.commit_group;");
    };

    issue(0);
    if (NT > 1) issue(1);

    for (int kt = 0; kt < NT; kt++) {
        if (kt + 1 < NT) asm volatile("cp.async.wait_group 1;");
        else             asm volatile("cp.async.wait_group 0;");
        __syncthreads();
        if (kt + 2 < NT) issue(kt + 2);

        const int s = kt % 3;
        const uint32_t asB = smA0 + s * A_STAGE * 2;
        const uint32_t bsB = smB0 + s * B_STAGE * 2;

#pragma unroll
        for (int ks = 0; ks < 4; ks++) {        // four k16 steps per BK=64
            const int kh = ks * 16;
            uint32_t af[4][4], bq[2][4];
#pragma unroll
            for (int mi = 0; mi < 4; mi++) {
                int row  = wm * 64 + mi * 16 + (grp & 1) * 8 + wi;
                int colh = kh + (grp >> 1) * 8;
                ldsm_x4(af[mi], asB + (uint32_t)(row * ASTRH + colh) * 2);
            }
#pragma unroll
            for (int p = 0; p < 2; p++) {
                int krow = kh + (grp & 1) * 8 + wi;
                int ncol = wn * 32 + p * 16 + (grp >> 1) * 8;
                ldsm_x4t(bq[p], bsB + (uint32_t)(krow * BSTRH + ncol) * 2);
            }
#pragma unroll
            for (int mi = 0; mi < 4; mi++) {
                mma_f16(acc[mi][0], af[mi], bq[0][0], bq[0][1]);
                mma_f16(acc[mi][1], af[mi], bq[0][2], bq[0][3]);
                mma_f16(acc[mi][2], af[mi], bq[1][0], bq[1][1]);
                mma_f16(acc[mi][3], af[mi], bq[1][2], bq[1][3]);
            }
        }
    }

#pragma unroll
    for (int mi = 0; mi < 4; mi++) {
#pragma unroll
        for (int ni = 0; ni < 4; ni++) {
            int r = m0 + wm * 64 + mi * 16 + g;
            int c = n0 + wn * 32 + ni * 8 + t * 2;
            if (OUTH) {
                __half* Ch = (__half*)Cv;
                *(uint32_t*)&Ch[(size_t)r * N + c]       = pkh(acc[mi][ni][0], acc[mi][ni][1]);
                *(uint32_t*)&Ch[(size_t)(r + 8) * N + c] = pkh(acc[mi][ni][2], acc[mi][ni][3]);
            } else {
                float* Cf = (float*)Cv;
                *(float2*)&Cf[(size_t)r * N + c]       = make_float2(acc[mi][ni][0], acc[mi][ni][1]);
                *(float2*)&Cf[(size_t)(r + 8) * N + c] = make_float2(acc[mi][ni][2], acc[mi][ni][3]);
            }
        }
    }
}

// ===========================================================================
// FUSED depthwise conv(k=3,pad1) + bias + SiLU + [Bt|Ct] projection.
// Block = 64 rows; K-loop over DINNER in 32-channel chunks.
// Per chunk: stage xr rows (with +-1 halo) in smem, conv+silu -> xs (fp32,
// unrounded) + g_xch (fp16), then accumulate Bt/Ct from xs.
// ===========================================================================
#define CB_ROWS 64
__global__ __launch_bounds__(256)
void conv_bc(const float* __restrict__ conv_w, const float* __restrict__ conv_b,
             const float* __restrict__ Wb, const float* __restrict__ Wc)
{
    __shared__ __half xrow[CB_ROWS + 2][40];   // halo rows, 32 chans (+pad)
    __shared__ float  xs[CB_ROWS][33];         // conv output fp32
    __shared__ float  ws[32][32];              // [W_B | W_C] chunk
    __shared__ float  cw[32][3];
    __shared__ float  cbia[32];

    const int row0 = blockIdx.x * CB_ROWS;     // global row; block within batch
    const int l0   = row0 & (SEQ - 1);
    const int tid  = threadIdx.x;
    const int tx   = tid & 31;                 // bc output column
    const int ty   = tid >> 5;                 // bc row group (8 rows each)

    float acc[8];
#pragma unroll
    for (int r = 0; r < 8; r++) acc[r] = 0.f;

    for (int k0 = 0; k0 < DINNER; k0 += 32) {
        __syncthreads();   // previous iteration's reads done before overwrite

        if (tid < 32) {
            cw[tid][0] = conv_w[(k0 + tid) * 3 + 0];
            cw[tid][1] = conv_w[(k0 + tid) * 3 + 1];
            cw[tid][2] = conv_w[(k0 + tid) * 3 + 2];
            cbia[tid]  = conv_b[k0 + tid];
        }
        {
            int lin = tid * 4;
            int kk = lin >> 5, c = lin & 31;
            float4 v;
            if (c < 16) v = *(const float4*)&Wb[(size_t)(k0 + kk) * 16 + c];
            else        v = *(const float4*)&Wc[(size_t)(k0 + kk) * 16 + (c - 16)];
            *(float4*)&ws[kk][c] = v;
        }
        // stage xr rows row0-1 .. row0+CB_ROWS (66 rows x 4 uint4 = 264 loads)
#pragma unroll
        for (int i = 0; i < 2; i++) {
            int idx = tid + i * 256;
            if (idx < (CB_ROWS + 2) * 4) {
                int r = idx >> 2, c8 = (idx & 3) * 8;
                int gl = l0 + r - 1;
                uint4 v = make_uint4(0, 0, 0, 0);
                if (gl >= 0 && gl < SEQ)
                    v = *(const uint4*)&g_xrh[(size_t)(row0 + r - 1) * (2*DINNER) + k0 + c8];
                *(uint4*)&xrow[r][c8] = v;
            }
        }
        __syncthreads();

        // conv + silu: thread -> (row = tid>>2, 8 chans)
        {
            int r  = tid >> 2;
            int c8 = (tid & 3) * 8;
            uint32_t outp[4];
#pragma unroll
            for (int p = 0; p < 4; p++) {
                int c = c8 + p * 2;
                float2 f0 = __half22float2(*(const __half2*)&xrow[r][c]);
                float2 f1 = __half22float2(*(const __half2*)&xrow[r + 1][c]);
                float2 f2 = __half22float2(*(const __half2*)&xrow[r + 2][c]);
                float a0 = f0.x * cw[c][0]     + f1.x * cw[c][1]     + f2.x * cw[c][2]     + cbia[c];
                float a1 = f0.y * cw[c + 1][0] + f1.y * cw[c + 1][1] + f2.y * cw[c + 1][2] + cbia[c + 1];
                float s0 = a0 / (1.f + expf(-a0));
                float s1 = a1 / (1.f + expf(-a1));
                xs[r][c]     = s0;
                xs[r][c + 1] = s1;
                outp[p] = pkh(s0, s1);
            }
            *(uint4*)&g_xch[(size_t)(row0 + r) * DINNER + k0 + c8] = *(uint4*)outp;
        }
        __syncthreads();

        // Bt/Ct accumulate
#pragma unroll
        for (int kk = 0; kk < 32; kk++) {
            float w = ws[kk][tx];
#pragma unroll
            for (int r = 0; r < 8; r++)
                acc[r] += xs[ty * 8 + r][kk] * w;
        }
    }

#pragma unroll
    for (int r = 0; r < 8; r++)
        g_bc[(size_t)(row0 + ty * 8 + r) * 32 + tx] = acc[r];
}

// ---------------------------------------------------------------------------
// Chunked scan: phase A (chunk end-states from 0), combine, phase C (replay).
// ---------------------------------------------------------------------------
__global__ void scan_phaseA(const float* __restrict__ A)
{
    __shared__ float bcs[CHUNK][32];
    const int b = blockIdx.x >> 5;
    const int c = blockIdx.x & 31;
    const int tid = threadIdx.x;

    const size_t base = (size_t)b * SEQ + (size_t)c * CHUNK;
    const size_t grow = (base + tid) * 32;
#pragma unroll
    for (int i = 0; i < 8; i++)
        *(float4*)&bcs[tid][i * 4] = *(const float4*)&g_bc[grow + i * 4];
    __syncthreads();

    if (tid < DSTATE) {
        float dec = 1.f / (1.f + expf(A[tid]));
        float st = 0.f;
        for (int l = 0; l < CHUNK; l++)
            st = fmaf(st, dec, bcs[l][tid]);
        g_E[(b * NCHUNK + c) * DSTATE + tid] = st;
    }
}

__global__ void scan_combine(const float* __restrict__ A)
{
    const int b = blockIdx.x;
    const int s = threadIdx.x;
    float dec  = 1.f / (1.f + expf(A[s]));
    float d128 = powf(dec, (float)CHUNK);
    float S = 0.f;
    for (int c = 0; c < NCHUNK; c++) {
        g_init[(b * NCHUNK + c) * DSTATE + s] = S;
        S = S * d128 + g_E[(b * NCHUNK + c) * DSTATE + s];
    }
}

__global__ void scan_phaseC(const float* __restrict__ A)
{
    __shared__ float bcs[CHUNK][32];
    const int b = blockIdx.x >> 5;
    const int c = blockIdx.x & 31;
    const int tid = threadIdx.x;

    const size_t base = (size_t)b * SEQ + (size_t)c * CHUNK;
    const size_t grow = (base + tid) * 32;
#pragma unroll
    for (int i = 0; i < 8; i++)
        *(float4*)&bcs[tid][i * 4] = *(const float4*)&g_bc[grow + i * 4];
    __syncthreads();

    if (tid < DSTATE) {
        float dec = 1.f / (1.f + expf(A[tid]));
        float st = g_init[(b * NCHUNK + c) * DSTATE + tid];
        for (int l = 0; l < CHUNK; l++) {
            st = fmaf(st, dec, bcs[l][tid]);
            float v = st * bcs[l][16 + tid];
#pragma unroll
            for (int m = 8; m >= 1; m >>= 1)
                v += __shfl_xor_sync(0x0000ffffu, v, m, 16);
            if (tid == 0) g_ys[base + l] = v;
        }
    }
}

// ---------------------------------------------------------------------------
// Gating elementwise (fp16 in/out), 16 chans per thread, 512-thread blocks:
//   yh = half((ys + xc*D) * silu(res))
// ---------------------------------------------------------------------------
__global__ __launch_bounds__(512)
void gate_y(const float* __restrict__ Dv)
{
    size_t vidx = (size_t)blockIdx.x * 512 + threadIdx.x;  // over BL*DINNER/16
    int c16 = (int)((vidx & (DINNER/16 - 1)) << 4);
    size_t row = vidx >> 7;                                // /(DINNER/16)
    float ysv = g_ys[row];

#pragma unroll
    for (int h = 0; h < 2; h++) {
        int cb = c16 + h * 8;
        uint4 uxc  = *(const uint4*)&g_xch[row * (size_t)DINNER + cb];
        uint4 ures = *(const uint4*)&g_xrh[row * (size_t)(2*DINNER) + DINNER + cb];
        const __half2* hxc  = (const __half2*)&uxc;
        const __half2* hres = (const __half2*)&ures;
        uint4 out;
        uint32_t* op = (uint32_t*)&out;
#pragma unroll
        for (int p = 0; p < 4; p++) {
            float2 xc  = __half22float2(hxc[p]);
            float2 res = __half22float2(hres[p]);
            int c = cb + p * 2;
            float y0 = (ysv + xc.x * Dv[c])     * (res.x / (1.f + expf(-res.x)));
            float y1 = (ysv + xc.y * Dv[c + 1]) * (res.y / (1.f + expf(-res.y)));
            op[p] = pkh(y0, y1);
        }
        *(uint4*)&g_yh[row * (size_t)DINNER + cb] = out;
    }
}

// ---------------------------------------------------------------------------
// Launch
// ---------------------------------------------------------------------------
extern "C" void kernel_launch(void* const* d_in, const int* in_sizes, int n_in,
                              void* d_out, int out_size)
{
    const float* x      = (const float*)d_in[0];
    const float* W_in   = (const float*)d_in[1];
    const float* conv_w = (const float*)d_in[2];
    const float* conv_b = (const float*)d_in[3];
    const float* W_B    = (const float*)d_in[4];
    const float* W_C    = (const float*)d_in[5];
    const float* A      = (const float*)d_in[6];
    const float* Dv     = (const float*)d_in[7];
    const float* W_out  = (const float*)d_in[8];
    float* out = (float*)d_out;

    __half *xh_p, *winh_p, *wouth_p, *xrh_p, *yh_p;
    cudaGetSymbolAddress((void**)&xh_p,   g_xh);
    cudaGetSymbolAddress((void**)&winh_p, g_Winh);
    cudaGetSymbolAddress((void**)&wouth_p,g_Wouth);
    cudaGetSymbolAddress((void**)&xrh_p,  g_xrh);
    cudaGetSymbolAddress((void**)&yh_p,   g_yh);

    cudaFuncSetAttribute(h16gemm_hh<true>,  cudaFuncAttributeMaxDynamicSharedMemorySize, GEMM_SMEM_BYTES);
    cudaFuncSetAttribute(h16gemm_hh<false>, cudaFuncAttributeMaxDynamicSharedMemorySize, GEMM_SMEM_BYTES);

    // 0) fp32 -> fp16 conversions (x, W_in, W_out)
    cvt_f32_f16<<<((size_t)BL * DMODEL / 8) / 256, 256>>>(x, xh_p);
    cvt_f32_f16<<<((size_t)DMODEL * 2*DINNER / 8) / 256, 256>>>(W_in, winh_p);
    cvt_f32_f16<<<((size_t)DINNER * DMODEL / 8) / 256, 256>>>(W_out, wouth_p);

    // 1) xr(fp16) = x @ W_in
    {
        dim3 grid((2*DINNER) / 128, BL / 128);
        h16gemm_hh<true><<<grid, 256, GEMM_SMEM_BYTES>>>(xh_p, winh_p, xrh_p, BL, 2*DINNER, DMODEL);
    }
    // 2+3) fused conv+silu+Bt/Ct -> g_xch, g_bc
    conv_bc<<<BL / CB_ROWS, 256>>>(conv_w, conv_b, W_B, W_C);
    // 4) chunked scan -> ys
    scan_phaseA<<<BATCH * NCHUNK, CHUNK>>>(A);
    scan_combine<<<BATCH, DSTATE>>>(A);
    scan_phaseC<<<BATCH * NCHUNK, CHUNK>>>(A);
    // 5) gating -> yh (fp16)
    gate_y<<<((size_t)BL * DINNER / 16) / 512, 512>>>(Dv);
    // 6) out(fp32) = yh @ W_out
    {
        dim3 grid(DMODEL / 128, BL / 128);
        h16gemm_hh<false><<<grid, 256, GEMM_SMEM_BYTES>>>(yh_p, wouth_p, out, BL, DMODEL, DINNER);
    }
}

// round 15
// speedup vs baseline: 1.3364x; 1.0090x over previous
#include <cuda_runtime.h>
#include <cuda_fp16.h>
#include <cstddef>
#include <cstdint>

// Problem constants
#define BATCH   4
#define SEQ     4096
#define DMODEL  1024
#define DSTATE  16
#define DINNER  2048
#define BL      (BATCH*SEQ)          // 16384 rows
#define NCHUNK  32                   // SEQ/128 scan chunks
#define CHUNK   128

// ---------------------------------------------------------------------------
// Scratch (device globals; allocation APIs are forbidden)
// ---------------------------------------------------------------------------
__device__ __half g_xh  [(size_t)BL * DMODEL];      // x in fp16          32MB
__device__ __half g_Winh[(size_t)DMODEL * 2*DINNER];// W_in fp16           8MB
__device__ __half g_Wouth[(size_t)DINNER * DMODEL]; // W_out fp16          4MB
__device__ __half g_xrh [(size_t)BL * (2*DINNER)];  // xr fp16 (main|res) 128MB
__device__ __half g_xch [(size_t)BL * DINNER];      // conv+silu fp16     64MB
__device__ __half g_yh  [(size_t)BL * DINNER];      // gated y fp16       64MB
__device__ float  g_bc[(size_t)BL * 32];            // [Bt | Ct]
__device__ float  g_ys[(size_t)BL];
__device__ float  g_E   [BATCH * NCHUNK * DSTATE];
__device__ float  g_init[BATCH * NCHUNK * DSTATE];

// ===========================================================================
// helpers
// ===========================================================================
#define HBK   64
#define ASTRH 72     // A smem row stride in halves (64 + 8 pad)
#define BSTRH 136    // B smem row stride in halves (128 + 8 pad)
#define A_STAGE (128 * ASTRH)            // halves
#define B_STAGE (HBK * BSTRH)            // halves
#define GEMM_SMEM_BYTES ((3 * (A_STAGE + B_STAGE)) * 2)

__device__ __forceinline__ uint32_t pkh(float a, float b) {
    __half2 h = __floats2half2_rn(a, b);
    return reinterpret_cast<uint32_t&>(h);
}

__device__ __forceinline__ uint32_t smem_u32(const void* p) {
    uint32_t a;
    asm("{ .reg .u64 t; cvta.to.shared.u64 t, %1; cvt.u32.u64 %0, t; }"
        : "=r"(a) : "l"(p));
    return a;
}

__device__ __forceinline__ void cpa16(uint32_t dst_smem, const void* src_gmem) {
    asm volatile("cp.async.cg.shared.global [%0], [%1], 16;"
                 :: "r"(dst_smem), "l"(src_gmem));
}

__device__ __forceinline__ void ldsm_x4(uint32_t r[4], uint32_t addr) {
    asm volatile("ldmatrix.sync.aligned.m8n8.x4.shared.b16 {%0,%1,%2,%3}, [%4];"
        : "=r"(r[0]), "=r"(r[1]), "=r"(r[2]), "=r"(r[3]) : "r"(addr));
}
__device__ __forceinline__ void ldsm_x4t(uint32_t r[4], uint32_t addr) {
    asm volatile("ldmatrix.sync.aligned.m8n8.x4.trans.shared.b16 {%0,%1,%2,%3}, [%4];"
        : "=r"(r[0]), "=r"(r[1]), "=r"(r[2]), "=r"(r[3]) : "r"(addr));
}

__device__ __forceinline__ void mma_f16(float d[4], const uint32_t a[4], const uint32_t b0, const uint32_t b1) {
    asm volatile(
        "mma.sync.aligned.m16n8k16.row.col.f32.f16.f16.f32 "
        "{%0,%1,%2,%3}, {%4,%5,%6,%7}, {%8,%9}, {%0,%1,%2,%3};\n"
        : "+f"(d[0]), "+f"(d[1]), "+f"(d[2]), "+f"(d[3])
        : "r"(a[0]), "r"(a[1]), "r"(a[2]), "r"(a[3]), "r"(b0), "r"(b1));
}

// ===========================================================================
// fp32 -> fp16 elementwise convert (8 elems/thread)
// ===========================================================================
__global__ void cvt_f32_f16(const float* __restrict__ src, __half* __restrict__ dst)
{
    size_t i8 = ((size_t)blockIdx.x * 256 + threadIdx.x) * 8;
    float4 a = *(const float4*)&src[i8];
    float4 b = *(const float4*)&src[i8 + 4];
    uint4 u = make_uint4(pkh(a.x, a.y), pkh(a.z, a.w), pkh(b.x, b.y), pkh(b.z, b.w));
    *(uint4*)&dst[i8] = u;
}

// ===========================================================================
// All-fp16-operand GEMM (frozen R13 config): 128x128 tile, BK=64,
// 256 threads, warp tile 64x32, 3-stage cp.async, ldmatrix + m16n8k16.
// ===========================================================================
template <bool OUTH>
__global__ __launch_bounds__(256)
void h16gemm_hh(const __half* __restrict__ A, const __half* __restrict__ B,
                void* __restrict__ Cv, int M, int N, int K)
{
    extern __shared__ char raw[];
    __half* smA = (__half*)raw;                       // 3 stages of A
    __half* smB = (__half*)raw + 3 * A_STAGE;         // 3 stages of B
    const uint32_t smA0 = smem_u32(smA);
    const uint32_t smB0 = smem_u32(smB);

    const int tid  = threadIdx.x;
    const int lane = tid & 31;
    const int wid  = tid >> 5;
    const int wm   = wid >> 2;
    const int wn   = wid & 3;
    const int m0   = blockIdx.y * 128;
    const int n0   = blockIdx.x * 128;
    const int g    = lane >> 2;
    const int t    = lane & 3;
    const int grp  = lane >> 3;
    const int wi   = lane & 7;

    float acc[4][4][4];
#pragma unroll
    for (int mi = 0; mi < 4; mi++)
#pragma unroll
        for (int ni = 0; ni < 4; ni++)
#pragma unroll
            for (int r = 0; r < 4; r++) acc[mi][ni][r] = 0.f;

    const int NT = K / HBK;

    auto issue = [&](int kt) {
        const int s = kt % 3;
        const uint32_t aB = smA0 + s * A_STAGE * 2;
        const __half* Ag = A + (size_t)m0 * K + kt * HBK;
#pragma unroll
        for (int i = 0; i < 4; i++) {
            int idx = tid + i * 256;            // 1024 chunks over 128 rows x 8
            int r = idx >> 3, c8 = (idx & 7) * 8;
            cpa16(aB + (uint32_t)(r * ASTRH + c8) * 2, Ag + (size_t)r * K + c8);
        }
        const uint32_t bB = smB0 + s * B_STAGE * 2;
        const __half* Bg = B + (size_t)(kt * HBK) * N + n0;
#pragma unroll
        for (int i = 0; i < 4; i++) {
            int idx = tid + i * 256;            // 1024 chunks over 64 rows x 16
            int kr = idx >> 4, c8 = (idx & 15) * 8;
            cpa16(bB + (uint32_t)(kr * BSTRH + c8) * 2, Bg + (size_t)kr * N + c8);
        }
        asm volatile("cp.async.commit_group;");
    };

    issue(0);
    if (NT > 1) issue(1);

    for (int kt = 0; kt < NT; kt++) {
        if (kt + 1 < NT) asm volatile("cp.async.wait_group 1;");
        else             asm volatile("cp.async.wait_group 0;");
        __syncthreads();
        if (kt + 2 < NT) issue(kt + 2);

        const int s = kt % 3;
        const uint32_t asB = smA0 + s * A_STAGE * 2;
        const uint32_t bsB = smB0 + s * B_STAGE * 2;

#pragma unroll
        for (int ks = 0; ks < 4; ks++) {        // four k16 steps per BK=64
            const int kh = ks * 16;
            uint32_t af[4][4], bq[2][4];
#pragma unroll
            for (int mi = 0; mi < 4; mi++) {
                int row  = wm * 64 + mi * 16 + (grp & 1) * 8 + wi;
                int colh = kh + (grp >> 1) * 8;
                ldsm_x4(af[mi], asB + (uint32_t)(row * ASTRH + colh) * 2);
            }
#pragma unroll
            for (int p = 0; p < 2; p++) {
                int krow = kh + (grp & 1) * 8 + wi;
                int ncol = wn * 32 + p * 16 + (grp >> 1) * 8;
                ldsm_x4t(bq[p], bsB + (uint32_t)(krow * BSTRH + ncol) * 2);
            }
#pragma unroll
            for (int mi = 0; mi < 4; mi++) {
                mma_f16(acc[mi][0], af[mi], bq[0][0], bq[0][1]);
                mma_f16(acc[mi][1], af[mi], bq[0][2], bq[0][3]);
                mma_f16(acc[mi][2], af[mi], bq[1][0], bq[1][1]);
                mma_f16(acc[mi][3], af[mi], bq[1][2], bq[1][3]);
            }
        }
    }

#pragma unroll
    for (int mi = 0; mi < 4; mi++) {
#pragma unroll
        for (int ni = 0; ni < 4; ni++) {
            int r = m0 + wm * 64 + mi * 16 + g;
            int c = n0 + wn * 32 + ni * 8 + t * 2;
            if (OUTH) {
                __half* Ch = (__half*)Cv;
                *(uint32_t*)&Ch[(size_t)r * N + c]       = pkh(acc[mi][ni][0], acc[mi][ni][1]);
                *(uint32_t*)&Ch[(size_t)(r + 8) * N + c] = pkh(acc[mi][ni][2], acc[mi][ni][3]);
            } else {
                float* Cf = (float*)Cv;
                *(float2*)&Cf[(size_t)r * N + c]       = make_float2(acc[mi][ni][0], acc[mi][ni][1]);
                *(float2*)&Cf[(size_t)(r + 8) * N + c] = make_float2(acc[mi][ni][2], acc[mi][ni][3]);
            }
        }
    }
}

// ===========================================================================
// FUSED depthwise conv(k=3,pad1) + bias + SiLU + [Bt|Ct] projection.
// Block = 64 rows; K-loop over DINNER in 64-channel chunks (32 iterations,
// 96 barriers vs 192 in the 32-chunk version). Per chunk: stage xr rows
// (+-1 halo) in smem, conv+silu -> xs (fp32) + g_xch (fp16), accumulate Bt/Ct.
// ===========================================================================
#define CB_ROWS 64
#define CB_CH   64
__global__ __launch_bounds__(256)
void conv_bc(const float* __restrict__ conv_w, const float* __restrict__ conv_b,
             const float* __restrict__ Wb, const float* __restrict__ Wc)
{
    __shared__ __half xrow[CB_ROWS + 2][CB_CH + 8];  // halo rows, 64 chans
    __shared__ float  xs[CB_ROWS][CB_CH + 1];        // conv output fp32
    __shared__ float  ws[CB_CH][32];                 // [W_B | W_C] chunk
    __shared__ float  cw[CB_CH][3];
    __shared__ float  cbia[CB_CH];

    const int row0 = blockIdx.x * CB_ROWS;
    const int l0   = row0 & (SEQ - 1);
    const int tid  = threadIdx.x;
    const int tx   = tid & 31;                 // bc output column
    const int ty   = tid >> 5;                 // bc row group (8 rows each)

    float acc[8];
#pragma unroll
    for (int r = 0; r < 8; r++) acc[r] = 0.f;

    for (int k0 = 0; k0 < DINNER; k0 += CB_CH) {
        __syncthreads();   // prev bc reads (xs, ws) + prev conv reads (xrow) done

        if (tid < CB_CH) {
            cw[tid][0] = conv_w[(k0 + tid) * 3 + 0];
            cw[tid][1] = conv_w[(k0 + tid) * 3 + 1];
            cw[tid][2] = conv_w[(k0 + tid) * 3 + 2];
            cbia[tid]  = conv_b[k0 + tid];
        }
        // ws: 64 k-rows x 32 cols = 512 float4
#pragma unroll
        for (int i = 0; i < 2; i++) {
            int lin = (tid + i * 256) * 4;
            int kk = lin >> 5, c = lin & 31;
            float4 v;
            if (c < 16) v = *(const float4*)&Wb[(size_t)(k0 + kk) * 16 + c];
            else        v = *(const float4*)&Wc[(size_t)(k0 + kk) * 16 + (c - 16)];
            *(float4*)&ws[kk][c] = v;
        }
        // stage xr rows row0-1 .. row0+CB_ROWS : 66 rows x 8 uint4 = 528
#pragma unroll
        for (int i = 0; i < 3; i++) {
            int idx = tid + i * 256;
            if (idx < (CB_ROWS + 2) * 8) {
                int r = idx >> 3, c8 = (idx & 7) * 8;
                int gl = l0 + r - 1;
                uint4 v = make_uint4(0, 0, 0, 0);
                if (gl >= 0 && gl < SEQ)
                    v = *(const uint4*)&g_xrh[(size_t)(row0 + r - 1) * (2*DINNER) + k0 + c8];
                *(uint4*)&xrow[r][c8] = v;
            }
        }
        __syncthreads();

        // conv + silu: thread -> (row = tid>>2, 16 chans)
        {
            int r   = tid >> 2;
            int c16 = (tid & 3) * 16;
            uint32_t outp[8];
#pragma unroll
            for (int p = 0; p < 8; p++) {
                int c = c16 + p * 2;
                float2 f0 = __half22float2(*(const __half2*)&xrow[r][c]);
                float2 f1 = __half22float2(*(const __half2*)&xrow[r + 1][c]);
                float2 f2 = __half22float2(*(const __half2*)&xrow[r + 2][c]);
                float a0 = f0.x * cw[c][0]     + f1.x * cw[c][1]     + f2.x * cw[c][2]     + cbia[c];
                float a1 = f0.y * cw[c + 1][0] + f1.y * cw[c + 1][1] + f2.y * cw[c + 1][2] + cbia[c + 1];
                float s0 = a0 / (1.f + expf(-a0));
                float s1 = a1 / (1.f + expf(-a1));
                xs[r][c]     = s0;
                xs[r][c + 1] = s1;
                outp[p] = pkh(s0, s1);
            }
            *(uint4*)&g_xch[(size_t)(row0 + r) * DINNER + k0 + c16]     = *(uint4*)&outp[0];
            *(uint4*)&g_xch[(size_t)(row0 + r) * DINNER + k0 + c16 + 8] = *(uint4*)&outp[4];
        }
        __syncthreads();

        // Bt/Ct accumulate over 64 k
#pragma unroll
        for (int kk = 0; kk < CB_CH; kk++) {
            float w = ws[kk][tx];
#pragma unroll
            for (int r = 0; r < 8; r++)
                acc[r] += xs[ty * 8 + r][kk] * w;
        }
    }

#pragma unroll
    for (int r = 0; r < 8; r++)
        g_bc[(size_t)(row0 + ty * 8 + r) * 32 + tx] = acc[r];
}

// ---------------------------------------------------------------------------
// Chunked scan: phase A (chunk end-states from 0), combine, phase C (replay).
// ---------------------------------------------------------------------------
__global__ void scan_phaseA(const float* __restrict__ A)
{
    __shared__ float bcs[CHUNK][32];
    const int b = blockIdx.x >> 5;
    const int c = blockIdx.x & 31;
    const int tid = threadIdx.x;

    const size_t base = (size_t)b * SEQ + (size_t)c * CHUNK;
    const size_t grow = (base + tid) * 32;
#pragma unroll
    for (int i = 0; i < 8; i++)
        *(float4*)&bcs[tid][i * 4] = *(const float4*)&g_bc[grow + i * 4];
    __syncthreads();

    if (tid < DSTATE) {
        float dec = 1.f / (1.f + expf(A[tid]));
        float st = 0.f;
        for (int l = 0; l < CHUNK; l++)
            st = fmaf(st, dec, bcs[l][tid]);
        g_E[(b * NCHUNK + c) * DSTATE + tid] = st;
    }
}

__global__ void scan_combine(const float* __restrict__ A)
{
    const int b = blockIdx.x;
    const int s = threadIdx.x;
    float dec  = 1.f / (1.f + expf(A[s]));
    float d128 = powf(dec, (float)CHUNK);
    float S = 0.f;
    for (int c = 0; c < NCHUNK; c++) {
        g_init[(b * NCHUNK + c) * DSTATE + s] = S;
        S = S * d128 + g_E[(b * NCHUNK + c) * DSTATE + s];
    }
}

__global__ void scan_phaseC(const float* __restrict__ A)
{
    __shared__ float bcs[CHUNK][32];
    const int b = blockIdx.x >> 5;
    const int c = blockIdx.x & 31;
    const int tid = threadIdx.x;

    const size_t base = (size_t)b * SEQ + (size_t)c * CHUNK;
    const size_t grow = (base + tid) * 32;
#pragma unroll
    for (int i = 0; i < 8; i++)
        *(float4*)&bcs[tid][i * 4] = *(const float4*)&g_bc[grow + i * 4];
    __syncthreads();

    if (tid < DSTATE) {
        float dec = 1.f / (1.f + expf(A[tid]));
        float st = g_init[(b * NCHUNK + c) * DSTATE + tid];
        for (int l = 0; l < CHUNK; l++) {
            st = fmaf(st, dec, bcs[l][tid]);
            float v = st * bcs[l][16 + tid];
#pragma unroll
            for (int m = 8; m >= 1; m >>= 1)
                v += __shfl_xor_sync(0x0000ffffu, v, m, 16);
            if (tid == 0) g_ys[base + l] = v;
        }
    }
}

// ---------------------------------------------------------------------------
// Gating elementwise (fp16 in/out), 16 chans per thread, 512-thread blocks:
//   yh = half((ys + xc*D) * silu(res))
// ---------------------------------------------------------------------------
__global__ __launch_bounds__(512)
void gate_y(const float* __restrict__ Dv)
{
    size_t vidx = (size_t)blockIdx.x * 512 + threadIdx.x;  // over BL*DINNER/16
    int c16 = (int)((vidx & (DINNER/16 - 1)) << 4);
    size_t row = vidx >> 7;                                // /(DINNER/16)
    float ysv = g_ys[row];

#pragma unroll
    for (int h = 0; h < 2; h++) {
        int cb = c16 + h * 8;
        uint4 uxc  = *(const uint4*)&g_xch[row * (size_t)DINNER + cb];
        uint4 ures = *(const uint4*)&g_xrh[row * (size_t)(2*DINNER) + DINNER + cb];
        const __half2* hxc  = (const __half2*)&uxc;
        const __half2* hres = (const __half2*)&ures;
        uint4 out;
        uint32_t* op = (uint32_t*)&out;
#pragma unroll
        for (int p = 0; p < 4; p++) {
            float2 xc  = __half22float2(hxc[p]);
            float2 res = __half22float2(hres[p]);
            int c = cb + p * 2;
            float y0 = (ysv + xc.x * Dv[c])     * (res.x / (1.f + expf(-res.x)));
            float y1 = (ysv + xc.y * Dv[c + 1]) * (res.y / (1.f + expf(-res.y)));
            op[p] = pkh(y0, y1);
        }
        *(uint4*)&g_yh[row * (size_t)DINNER + cb] = out;
    }
}

// ---------------------------------------------------------------------------
// Launch
// ---------------------------------------------------------------------------
extern "C" void kernel_launch(void* const* d_in, const int* in_sizes, int n_in,
                              void* d_out, int out_size)
{
    const float* x      = (const float*)d_in[0];
    const float* W_in   = (const float*)d_in[1];
    const float* conv_w = (const float*)d_in[2];
    const float* conv_b = (const float*)d_in[3];
    const float* W_B    = (const float*)d_in[4];
    const float* W_C    = (const float*)d_in[5];
    const float* A      = (const float*)d_in[6];
    const float* Dv     = (const float*)d_in[7];
    const float* W_out  = (const float*)d_in[8];
    float* out = (float*)d_out;

    __half *xh_p, *winh_p, *wouth_p, *xrh_p, *yh_p;
    cudaGetSymbolAddress((void**)&xh_p,   g_xh);
    cudaGetSymbolAddress((void**)&winh_p, g_Winh);
    cudaGetSymbolAddress((void**)&wouth_p,g_Wouth);
    cudaGetSymbolAddress((void**)&xrh_p,  g_xrh);
    cudaGetSymbolAddress((void**)&yh_p,   g_yh);

    cudaFuncSetAttribute(h16gemm_hh<true>,  cudaFuncAttributeMaxDynamicSharedMemorySize, GEMM_SMEM_BYTES);
    cudaFuncSetAttribute(h16gemm_hh<false>, cudaFuncAttributeMaxDynamicSharedMemorySize, GEMM_SMEM_BYTES);

    // 0) fp32 -> fp16 conversions (x, W_in, W_out)
    cvt_f32_f16<<<((size_t)BL * DMODEL / 8) / 256, 256>>>(x, xh_p);
    cvt_f32_f16<<<((size_t)DMODEL * 2*DINNER / 8) / 256, 256>>>(W_in, winh_p);
    cvt_f32_f16<<<((size_t)DINNER * DMODEL / 8) / 256, 256>>>(W_out, wouth_p);

    // 1) xr(fp16) = x @ W_in
    {
        dim3 grid((2*DINNER) / 128, BL / 128);
        h16gemm_hh<true><<<grid, 256, GEMM_SMEM_BYTES>>>(xh_p, winh_p, xrh_p, BL, 2*DINNER, DMODEL);
    }
    // 2+3) fused conv+silu+Bt/Ct -> g_xch, g_bc (64-channel chunks)
    conv_bc<<<BL / CB_ROWS, 256>>>(conv_w, conv_b, W_B, W_C);
    // 4) chunked scan -> ys
    scan_phaseA<<<BATCH * NCHUNK, CHUNK>>>(A);
    scan_combine<<<BATCH, DSTATE>>>(A);
    scan_phaseC<<<BATCH * NCHUNK, CHUNK>>>(A);
    // 5) gating -> yh (fp16)
    gate_y<<<((size_t)BL * DINNER / 16) / 512, 512>>>(Dv);
    // 6) out(fp32) = yh @ W_out
    {
        dim3 grid(DMODEL / 128, BL / 128);
        h16gemm_hh<false><<<grid, 256, GEMM_SMEM_BYTES>>>(yh_p, wouth_p, out, BL, DMODEL, DINNER);
    }
}

// round 16
// speedup vs baseline: 1.3398x; 1.0025x over previous
#include <cuda_runtime.h>
#include <cuda_fp16.h>
#include <cstddef>
#include <cstdint>

// Problem constants
#define BATCH   4
#define SEQ     4096
#define DMODEL  1024
#define DSTATE  16
#define DINNER  2048
#define BL      (BATCH*SEQ)          // 16384 rows
#define NCHUNK  32                   // SEQ/128 scan chunks
#define CHUNK   128

// ---------------------------------------------------------------------------
// Scratch (device globals; allocation APIs are forbidden)
// ---------------------------------------------------------------------------
__device__ __half g_xh  [(size_t)BL * DMODEL];      // x in fp16          32MB
__device__ __half g_Winh[(size_t)DMODEL * 2*DINNER];// W_in fp16           8MB
__device__ __half g_Wouth[(size_t)DINNER * DMODEL]; // W_out fp16          4MB
__device__ __half g_xrh [(size_t)BL * (2*DINNER)];  // xr fp16 (main|res) 128MB
__device__ __half g_xch [(size_t)BL * DINNER];      // conv+silu fp16     64MB
__device__ __half g_yh  [(size_t)BL * DINNER];      // gated y fp16       64MB
__device__ float  g_bc[(size_t)BL * 32];            // [Bt | Ct]
__device__ float  g_ys[(size_t)BL];
__device__ float  g_E   [BATCH * NCHUNK * DSTATE];
__device__ float  g_init[BATCH * NCHUNK * DSTATE];

// ===========================================================================
// helpers
// ===========================================================================
#define HBK   64
#define ASTRH 72     // A smem row stride in halves (64 + 8 pad)
#define BSTRH 136    // B smem row stride in halves (128 + 8 pad)
#define A_STAGE (128 * ASTRH)            // halves
#define B_STAGE (HBK * BSTRH)            // halves
#define GEMM_SMEM_BYTES ((3 * (A_STAGE + B_STAGE)) * 2)

__device__ __forceinline__ uint32_t pkh(float a, float b) {
    __half2 h = __floats2half2_rn(a, b);
    return reinterpret_cast<uint32_t&>(h);
}

__device__ __forceinline__ uint32_t smem_u32(const void* p) {
    uint32_t a;
    asm("{ .reg .u64 t; cvta.to.shared.u64 t, %1; cvt.u32.u64 %0, t; }"
        : "=r"(a) : "l"(p));
    return a;
}

// .cg: bypass L1 (streams). .ca: keep in L1 (cross-CTA A-tile reuse).
__device__ __forceinline__ void cpa16_cg(uint32_t dst_smem, const void* src_gmem) {
    asm volatile("cp.async.cg.shared.global [%0], [%1], 16;"
                 :: "r"(dst_smem), "l"(src_gmem));
}
__device__ __forceinline__ void cpa16_ca(uint32_t dst_smem, const void* src_gmem) {
    asm volatile("cp.async.ca.shared.global [%0], [%1], 16;"
                 :: "r"(dst_smem), "l"(src_gmem));
}

__device__ __forceinline__ void ldsm_x4(uint32_t r[4], uint32_t addr) {
    asm volatile("ldmatrix.sync.aligned.m8n8.x4.shared.b16 {%0,%1,%2,%3}, [%4];"
        : "=r"(r[0]), "=r"(r[1]), "=r"(r[2]), "=r"(r[3]) : "r"(addr));
}
__device__ __forceinline__ void ldsm_x4t(uint32_t r[4], uint32_t addr) {
    asm volatile("ldmatrix.sync.aligned.m8n8.x4.trans.shared.b16 {%0,%1,%2,%3}, [%4];"
        : "=r"(r[0]), "=r"(r[1]), "=r"(r[2]), "=r"(r[3]) : "r"(addr));
}

__device__ __forceinline__ void mma_f16(float d[4], const uint32_t a[4], const uint32_t b0, const uint32_t b1) {
    asm volatile(
        "mma.sync.aligned.m16n8k16.row.col.f32.f16.f16.f32 "
        "{%0,%1,%2,%3}, {%4,%5,%6,%7}, {%8,%9}, {%0,%1,%2,%3};\n"
        : "+f"(d[0]), "+f"(d[1]), "+f"(d[2]), "+f"(d[3])
        : "r"(a[0]), "r"(a[1]), "r"(a[2]), "r"(a[3]), "r"(b0), "r"(b1));
}

// ===========================================================================
// Single fused fp32 -> fp16 convert over x | W_in | W_out (8 elems/thread)
// ===========================================================================
#define CVT_S1 ((size_t)BL * DMODEL)            // x
#define CVT_S2 ((size_t)DMODEL * 2*DINNER)      // W_in
#define CVT_S3 ((size_t)DINNER * DMODEL)        // W_out
#define CVT_TOTAL (CVT_S1 + CVT_S2 + CVT_S3)

__global__ void cvt_all(const float* __restrict__ x, const float* __restrict__ Win,
                        const float* __restrict__ Wout)
{
    size_t i8 = ((size_t)blockIdx.x * 256 + threadIdx.x) * 8;
    const float* src;
    __half* dst;
    size_t off;
    if (i8 < CVT_S1)                 { src = x;    dst = g_xh;    off = i8; }
    else if (i8 < CVT_S1 + CVT_S2)   { src = Win;  dst = g_Winh;  off = i8 - CVT_S1; }
    else                             { src = Wout; dst = g_Wouth; off = i8 - CVT_S1 - CVT_S2; }

    float4 a = *(const float4*)&src[off];
    float4 b = *(const float4*)&src[off + 4];
    uint4 u = make_uint4(pkh(a.x, a.y), pkh(a.z, a.w), pkh(b.x, b.y), pkh(b.z, b.w));
    *(uint4*)&dst[off] = u;
}

// ===========================================================================
// All-fp16-operand GEMM (frozen R13 config): 128x128 tile, BK=64,
// 256 threads, warp tile 64x32, 3-stage cp.async, ldmatrix + m16n8k16.
// A loads use .ca (sibling-CTA L1 reuse), B loads .cg.
// ===========================================================================
template <bool OUTH>
__global__ __launch_bounds__(256)
void h16gemm_hh(const __half* __restrict__ A, const __half* __restrict__ B,
                void* __restrict__ Cv, int M, int N, int K)
{
    extern __shared__ char raw[];
    __half* smA = (__half*)raw;                       // 3 stages of A
    __half* smB = (__half*)raw + 3 * A_STAGE;         // 3 stages of B
    const uint32_t smA0 = smem_u32(smA);
    const uint32_t smB0 = smem_u32(smB);

    const int tid  = threadIdx.x;
    const int lane = tid & 31;
    const int wid  = tid >> 5;
    const int wm   = wid >> 2;
    const int wn   = wid & 3;
    const int m0   = blockIdx.y * 128;
    const int n0   = blockIdx.x * 128;
    const int g    = lane >> 2;
    const int t    = lane & 3;
    const int grp  = lane >> 3;
    const int wi   = lane & 7;

    float acc[4][4][4];
#pragma unroll
    for (int mi = 0; mi < 4; mi++)
#pragma unroll
        for (int ni = 0; ni < 4; ni++)
#pragma unroll
            for (int r = 0; r < 4; r++) acc[mi][ni][r] = 0.f;

    const int NT = K / HBK;

    auto issue = [&](int kt) {
        const int s = kt % 3;
        const uint32_t aB = smA0 + s * A_STAGE * 2;
        const __half* Ag = A + (size_t)m0 * K + kt * HBK;
#pragma unroll
        for (int i = 0; i < 4; i++) {
            int idx = tid + i * 256;            // 1024 chunks over 128 rows x 8
            int r = idx >> 3, c8 = (idx & 7) * 8;
            cpa16_ca(aB + (uint32_t)(r * ASTRH + c8) * 2, Ag + (size_t)r * K + c8);
        }
        const uint32_t bB = smB0 + s * B_STAGE * 2;
        const __half* Bg = B + (size_t)(kt * HBK) * N + n0;
#pragma unroll
        for (int i = 0; i < 4; i++) {
            int idx = tid + i * 256;            // 1024 chunks over 64 rows x 16
            int kr = idx >> 4, c8 = (idx & 15) * 8;
            cpa16_cg(bB + (uint32_t)(kr * BSTRH + c8) * 2, Bg + (size_t)kr * N + c8);
        }
        asm volatile("cp.async.commit_group;");
    };

    issue(0);
    if (NT > 1) issue(1);

    for (int kt = 0; kt < NT; kt++) {
        if (kt + 1 < NT) asm volatile("cp.async.wait_group 1;");
        else             asm volatile("cp.async.wait_group 0;");
        __syncthreads();
        if (kt + 2 < NT) issue(kt + 2);

        const int s = kt % 3;
        const uint32_t asB = smA0 + s * A_STAGE * 2;
        const uint32_t bsB = smB0 + s * B_STAGE * 2;

#pragma unroll
        for (int ks = 0; ks < 4; ks++) {        // four k16 steps per BK=64
            const int kh = ks * 16;
            uint32_t af[4][4], bq[2][4];
#pragma unroll
            for (int mi = 0; mi < 4; mi++) {
                int row  = wm * 64 + mi * 16 + (grp & 1) * 8 + wi;
                int colh = kh + (grp >> 1) * 8;
                ldsm_x4(af[mi], asB + (uint32_t)(row * ASTRH + colh) * 2);
            }
#pragma unroll
            for (int p = 0; p < 2; p++) {
                int krow = kh + (grp & 1) * 8 + wi;
                int ncol = wn * 32 + p * 16 + (grp >> 1) * 8;
                ldsm_x4t(bq[p], bsB + (uint32_t)(krow * BSTRH + ncol) * 2);
            }
#pragma unroll
            for (int mi = 0; mi < 4; mi++) {
                mma_f16(acc[mi][0], af[mi], bq[0][0], bq[0][1]);
                mma_f16(acc[mi][1], af[mi], bq[0][2], bq[0][3]);
                mma_f16(acc[mi][2], af[mi], bq[1][0], bq[1][1]);
                mma_f16(acc[mi][3], af[mi], bq[1][2], bq[1][3]);
            }
        }
    }

#pragma unroll
    for (int mi = 0; mi < 4; mi++) {
#pragma unroll
        for (int ni = 0; ni < 4; ni++) {
            int r = m0 + wm * 64 + mi * 16 + g;
            int c = n0 + wn * 32 + ni * 8 + t * 2;
            if (OUTH) {
                __half* Ch = (__half*)Cv;
                *(uint32_t*)&Ch[(size_t)r * N + c]       = pkh(acc[mi][ni][0], acc[mi][ni][1]);
                *(uint32_t*)&Ch[(size_t)(r + 8) * N + c] = pkh(acc[mi][ni][2], acc[mi][ni][3]);
            } else {
                float* Cf = (float*)Cv;
                *(float2*)&Cf[(size_t)r * N + c]       = make_float2(acc[mi][ni][0], acc[mi][ni][1]);
                *(float2*)&Cf[(size_t)(r + 8) * N + c] = make_float2(acc[mi][ni][2], acc[mi][ni][3]);
            }
        }
    }
}

// ===========================================================================
// FUSED depthwise conv(k=3,pad1) + bias + SiLU + [Bt|Ct] projection.
// Block = 64 rows; K-loop in 64-channel chunks.
// ===========================================================================
#define CB_ROWS 64
#define CB_CH   64
__global__ __launch_bounds__(256)
void conv_bc(const float* __restrict__ conv_w, const float* __restrict__ conv_b,
             const float* __restrict__ Wb, const float* __restrict__ Wc)
{
    __shared__ __half xrow[CB_ROWS + 2][CB_CH + 8];  // halo rows, 64 chans
    __shared__ float  xs[CB_ROWS][CB_CH + 1];        // conv output fp32
    __shared__ float  ws[CB_CH][32];                 // [W_B | W_C] chunk
    __shared__ float  cw[CB_CH][3];
    __shared__ float  cbia[CB_CH];

    const int row0 = blockIdx.x * CB_ROWS;
    const int l0   = row0 & (SEQ - 1);
    const int tid  = threadIdx.x;
    const int tx   = tid & 31;                 // bc output column
    const int ty   = tid >> 5;                 // bc row group (8 rows each)

    float acc[8];
#pragma unroll
    for (int r = 0; r < 8; r++) acc[r] = 0.f;

    for (int k0 = 0; k0 < DINNER; k0 += CB_CH) {
        __syncthreads();   // prev bc reads (xs, ws) + prev conv reads (xrow) done

        if (tid < CB_CH) {
            cw[tid][0] = conv_w[(k0 + tid) * 3 + 0];
            cw[tid][1] = conv_w[(k0 + tid) * 3 + 1];
            cw[tid][2] = conv_w[(k0 + tid) * 3 + 2];
            cbia[tid]  = conv_b[k0 + tid];
        }
        // ws: 64 k-rows x 32 cols = 512 float4
#pragma unroll
        for (int i = 0; i < 2; i++) {
            int lin = (tid + i * 256) * 4;
            int kk = lin >> 5, c = lin & 31;
            float4 v;
            if (c < 16) v = *(const float4*)&Wb[(size_t)(k0 + kk) * 16 + c];
            else        v = *(const float4*)&Wc[(size_t)(k0 + kk) * 16 + (c - 16)];
            *(float4*)&ws[kk][c] = v;
        }
        // stage xr rows row0-1 .. row0+CB_ROWS : 66 rows x 8 uint4 = 528
#pragma unroll
        for (int i = 0; i < 3; i++) {
            int idx = tid + i * 256;
            if (idx < (CB_ROWS + 2) * 8) {
                int r = idx >> 3, c8 = (idx & 7) * 8;
                int gl = l0 + r - 1;
                uint4 v = make_uint4(0, 0, 0, 0);
                if (gl >= 0 && gl < SEQ)
                    v = *(const uint4*)&g_xrh[(size_t)(row0 + r - 1) * (2*DINNER) + k0 + c8];
                *(uint4*)&xrow[r][c8] = v;
            }
        }
        __syncthreads();

        // conv + silu: thread -> (row = tid>>2, 16 chans)
        {
            int r   = tid >> 2;
            int c16 = (tid & 3) * 16;
            uint32_t outp[8];
#pragma unroll
            for (int p = 0; p < 8; p++) {
                int c = c16 + p * 2;
                float2 f0 = __half22float2(*(const __half2*)&xrow[r][c]);
                float2 f1 = __half22float2(*(const __half2*)&xrow[r + 1][c]);
                float2 f2 = __half22float2(*(const __half2*)&xrow[r + 2][c]);
                float a0 = f0.x * cw[c][0]     + f1.x * cw[c][1]     + f2.x * cw[c][2]     + cbia[c];
                float a1 = f0.y * cw[c + 1][0] + f1.y * cw[c + 1][1] + f2.y * cw[c + 1][2] + cbia[c + 1];
                float s0 = a0 / (1.f + expf(-a0));
                float s1 = a1 / (1.f + expf(-a1));
                xs[r][c]     = s0;
                xs[r][c + 1] = s1;
                outp[p] = pkh(s0, s1);
            }
            *(uint4*)&g_xch[(size_t)(row0 + r) * DINNER + k0 + c16]     = *(uint4*)&outp[0];
            *(uint4*)&g_xch[(size_t)(row0 + r) * DINNER + k0 + c16 + 8] = *(uint4*)&outp[4];
        }
        __syncthreads();

        // Bt/Ct accumulate over 64 k
#pragma unroll
        for (int kk = 0; kk < CB_CH; kk++) {
            float w = ws[kk][tx];
#pragma unroll
            for (int r = 0; r < 8; r++)
                acc[r] += xs[ty * 8 + r][kk] * w;
        }
    }

#pragma unroll
    for (int r = 0; r < 8; r++)
        g_bc[(size_t)(row0 + ty * 8 + r) * 32 + tx] = acc[r];
}

// ---------------------------------------------------------------------------
// Chunked scan: phase A (chunk end-states from 0), combine, phase C (replay).
// ---------------------------------------------------------------------------
__global__ void scan_phaseA(const float* __restrict__ A)
{
    __shared__ float bcs[CHUNK][32];
    const int b = blockIdx.x >> 5;
    const int c = blockIdx.x & 31;
    const int tid = threadIdx.x;

    const size_t base = (size_t)b * SEQ + (size_t)c * CHUNK;
    const size_t grow = (base + tid) * 32;
#pragma unroll
    for (int i = 0; i < 8; i++)
        *(float4*)&bcs[tid][i * 4] = *(const float4*)&g_bc[grow + i * 4];
    __syncthreads();

    if (tid < DSTATE) {
        float dec = 1.f / (1.f + expf(A[tid]));
        float st = 0.f;
        for (int l = 0; l < CHUNK; l++)
            st = fmaf(st, dec, bcs[l][tid]);
        g_E[(b * NCHUNK + c) * DSTATE + tid] = st;
    }
}

__global__ void scan_combine(const float* __restrict__ A)
{
    const int b = blockIdx.x;
    const int s = threadIdx.x;
    float dec  = 1.f / (1.f + expf(A[s]));
    float d128 = powf(dec, (float)CHUNK);
    float S = 0.f;
    for (int c = 0; c < NCHUNK; c++) {
        g_init[(b * NCHUNK + c) * DSTATE + s] = S;
        S = S * d128 + g_E[(b * NCHUNK + c) * DSTATE + s];
    }
}

__global__ void scan_phaseC(const float* __restrict__ A)
{
    __shared__ float bcs[CHUNK][32];
    const int b = blockIdx.x >> 5;
    const int c = blockIdx.x & 31;
    const int tid = threadIdx.x;

    const size_t base = (size_t)b * SEQ + (size_t)c * CHUNK;
    const size_t grow = (base + tid) * 32;
#pragma unroll
    for (int i = 0; i < 8; i++)
        *(float4*)&bcs[tid][i * 4] = *(const float4*)&g_bc[grow + i * 4];
    __syncthreads();

    if (tid < DSTATE) {
        float dec = 1.f / (1.f + expf(A[tid]));
        float st = g_init[(b * NCHUNK + c) * DSTATE + tid];
        for (int l = 0; l < CHUNK; l++) {
            st = fmaf(st, dec, bcs[l][tid]);
            float v = st * bcs[l][16 + tid];
#pragma unroll
            for (int m = 8; m >= 1; m >>= 1)
                v += __shfl_xor_sync(0x0000ffffu, v, m, 16);
            if (tid == 0) g_ys[base + l] = v;
        }
    }
}

// ---------------------------------------------------------------------------
// Gating elementwise (fp16 in/out), 16 chans per thread, 512-thread blocks:
//   yh = half((ys + xc*D) * silu(res))
// ---------------------------------------------------------------------------
__global__ __launch_bounds__(512)
void gate_y(const float* __restrict__ Dv)
{
    size_t vidx = (size_t)blockIdx.x * 512 + threadIdx.x;  // over BL*DINNER/16
    int c16 = (int)((vidx & (DINNER/16 - 1)) << 4);
    size_t row = vidx >> 7;                                // /(DINNER/16)
    float ysv = g_ys[row];

#pragma unroll
    for (int h = 0; h < 2; h++) {
        int cb = c16 + h * 8;
        uint4 uxc  = *(const uint4*)&g_xch[row * (size_t)DINNER + cb];
        uint4 ures = *(const uint4*)&g_xrh[row * (size_t)(2*DINNER) + DINNER + cb];
        const __half2* hxc  = (const __half2*)&uxc;
        const __half2* hres = (const __half2*)&ures;
        uint4 out;
        uint32_t* op = (uint32_t*)&out;
#pragma unroll
        for (int p = 0; p < 4; p++) {
            float2 xc  = __half22float2(hxc[p]);
            float2 res = __half22float2(hres[p]);
            int c = cb + p * 2;
            float y0 = (ysv + xc.x * Dv[c])     * (res.x / (1.f + expf(-res.x)));
            float y1 = (ysv + xc.y * Dv[c + 1]) * (res.y / (1.f + expf(-res.y)));
            op[p] = pkh(y0, y1);
        }
        *(uint4*)&g_yh[row * (size_t)DINNER + cb] = out;
    }
}

// ---------------------------------------------------------------------------
// Launch
// ---------------------------------------------------------------------------
extern "C" void kernel_launch(void* const* d_in, const int* in_sizes, int n_in,
                              void* d_out, int out_size)
{
    const float* x      = (const float*)d_in[0];
    const float* W_in   = (const float*)d_in[1];
    const float* conv_w = (const float*)d_in[2];
    const float* conv_b = (const float*)d_in[3];
    const float* W_B    = (const float*)d_in[4];
    const float* W_C    = (const float*)d_in[5];
    const float* A      = (const float*)d_in[6];
    const float* Dv     = (const float*)d_in[7];
    const float* W_out  = (const float*)d_in[8];
    float* out = (float*)d_out;

    __half *xh_p, *winh_p, *wouth_p, *xrh_p, *yh_p;
    cudaGetSymbolAddress((void**)&xh_p,   g_xh);
    cudaGetSymbolAddress((void**)&winh_p, g_Winh);
    cudaGetSymbolAddress((void**)&wouth_p,g_Wouth);
    cudaGetSymbolAddress((void**)&xrh_p,  g_xrh);
    cudaGetSymbolAddress((void**)&yh_p,   g_yh);

    cudaFuncSetAttribute(h16gemm_hh<true>,  cudaFuncAttributeMaxDynamicSharedMemorySize, GEMM_SMEM_BYTES);
    cudaFuncSetAttribute(h16gemm_hh<false>, cudaFuncAttributeMaxDynamicSharedMemorySize, GEMM_SMEM_BYTES);

    // 0) fused fp32 -> fp16 conversions (x | W_in | W_out), one launch
    cvt_all<<<(unsigned)((CVT_TOTAL / 8 + 255) / 256), 256>>>(x, W_in, W_out);

    // 1) xr(fp16) = x @ W_in
    {
        dim3 grid((2*DINNER) / 128, BL / 128);
        h16gemm_hh<true><<<grid, 256, GEMM_SMEM_BYTES>>>(xh_p, winh_p, xrh_p, BL, 2*DINNER, DMODEL);
    }
    // 2+3) fused conv+silu+Bt/Ct -> g_xch, g_bc
    conv_bc<<<BL / CB_ROWS, 256>>>(conv_w, conv_b, W_B, W_C);
    // 4) chunked scan -> ys
    scan_phaseA<<<BATCH * NCHUNK, CHUNK>>>(A);
    scan_combine<<<BATCH, DSTATE>>>(A);
    scan_phaseC<<<BATCH * NCHUNK, CHUNK>>>(A);
    // 5) gating -> yh (fp16)
    gate_y<<<((size_t)BL * DINNER / 16) / 512, 512>>>(Dv);
    // 6) out(fp32) = yh @ W_out
    {
        dim3 grid(DMODEL / 128, BL / 128);
        h16gemm_hh<false><<<grid, 256, GEMM_SMEM_BYTES>>>(yh_p, wouth_p, out, BL, DMODEL, DINNER);
    }
}